// round 12
// baseline (speedup 1.0000x reference)
#include <cuda_runtime.h>
#include <cuda_bf16.h>
#include <cstdint>

#define NN 10000
#define EE 160000
#define TEN 65536
#define EA (EE + NN)   // edges + self loops = 170000

// ---------------- scratch (static device globals; no allocation) ----------------
__device__ float g_w1p[4 * 384 * 384]; // split-K partials of fc1_w @ gat1_w
__device__ float g_w1c[384 * 384];     // summed + tf32-rounded (by fillk)
__device__ float g_b1c[384];           // fc1_b @ gat1_w
__device__ float g_w5r[384 * 256];     // tf32-rounded fc5_w
__device__ float g_wg2r[256 * 256];    // tf32-rounded gat2_w
__device__ float g_w2r[256 * 256];     // tf32-rounded fc2_w
__device__ float g_h1[NN * 384];
__device__ float g_gout1[NN * 384];
__device__ float g_h5[NN * 256];
__device__ float g_h2[NN * 256];
__device__ float g_gout2[NN * 256];
__device__ float g_hf[NN * 256];

__device__ float g_as1[NN * 8], g_ad1[NN * 8];
__device__ float g_as2[NN], g_ad2[NN];
__device__ float g_psum1[16 * 384], g_pss1[16 * 384];
__device__ float g_psum2[16 * 256], g_pss2[16 * 256];
__device__ float2 g_cc1[384], g_cc2[256];   // {scale, shift} per column

// CSR by destination (shared by both GAT layers)
__device__ int g_deg[NN];
__device__ int g_off[NN + 1];
__device__ int g_pos[NN];
__device__ int g_srcl[EA];
__device__ int g_ctr[3];   // [0]=degk cnt, [1]/[2]=bnpf cnt

// ---------------- helpers ----------------
__device__ __forceinline__ void edge_sd(const int* __restrict__ ei, int e, int& s, int& d) {
    if (e < EE) { s = ei[e]; d = ei[EE + e]; }
    else        { s = e - EE; d = e - EE; }
}

__device__ __forceinline__ float leaky(float v) { return v > 0.f ? v : 0.2f * v; }

__device__ __forceinline__ uint32_t f2tf32(float v) {
    uint32_t u;
    asm("cvt.rna.tf32.f32 %0, %1;" : "=r"(u) : "f"(v));
    return u;
}

__device__ __forceinline__ void cp_async16(uint32_t dst_s, const void* src) {
    asm volatile("cp.async.cg.shared.global [%0], [%1], 16;\n" :: "r"(dst_s), "l"(src));
}
__device__ __forceinline__ void cp_async16z(uint32_t dst_s, const void* src, int sz) {
    asm volatile("cp.async.cg.shared.global [%0], [%1], 16, %2;\n"
                 :: "r"(dst_s), "l"(src), "r"(sz));
}

// ---------------- setupA: zero counters + coef accumulators ----------------
__global__ void setupA() {
    int i = blockIdx.x * blockDim.x + threadIdx.x;
    if (i < NN * 8) { g_as1[i] = 0.f; g_ad1[i] = 0.f; }
    if (i < NN) { g_deg[i] = 0; g_as2[i] = 0.f; g_ad2[i] = 0.f; }
    if (i < 3) g_ctr[i] = 0;
}

// ---------------- setupB: merged independent prep jobs ----------------
#define NB_G 144
#define NB_BC 2
#define NB_R5 384
#define NB_RG 256
#define NB_R2 256
#define NB_DEG 665
#define B_BC   (NB_G)
#define B_R5   (B_BC + NB_BC)
#define B_RG   (B_R5 + NB_R5)
#define B_R2   (B_RG + NB_RG)
#define B_DEG  (B_R2 + NB_R2)
#define NB_ALL (B_DEG + NB_DEG)

__global__ void __launch_bounds__(256) setupB(
    const float* __restrict__ fc1_w, const float* __restrict__ gat1_w,
    const float* __restrict__ fc1_b,
    const float* __restrict__ fc5_w, const float* __restrict__ gat2_w,
    const float* __restrict__ fc2_w, const int* __restrict__ ei)
{
    const int b = blockIdx.x;
    const int t = threadIdx.x;

    if (b < NB_G) {
        // ---- fp32 split-K 384^3 weight-fuse tile: write partial (deterministic) ----
        __shared__ float As[16][64];
        __shared__ float Bs[16][64];
        int q = b;
        int z = q & 3; q >>= 2;
        int bx = q % 6, by = q / 6;
        const int m0 = by * 64, n0 = bx * 64;
        const int kbeg = z * 96, kend = kbeg + 96;
        const int tx = t & 15, ty = t >> 4;
        const int la_m = t >> 2, la_k = (t & 3) * 4;
        const int lb_k = t >> 4, lb_n = (t & 15) * 4;
        float acc[4][4] = {};
        for (int k0 = kbeg; k0 < kend; k0 += 16) {
            float4 av = *(const float4*)&fc1_w[(size_t)(m0 + la_m) * 384 + k0 + la_k];
            As[la_k + 0][la_m] = av.x; As[la_k + 1][la_m] = av.y;
            As[la_k + 2][la_m] = av.z; As[la_k + 3][la_m] = av.w;
            *(float4*)&Bs[lb_k][lb_n] =
                *(const float4*)&gat1_w[(size_t)(k0 + lb_k) * 384 + n0 + lb_n];
            __syncthreads();
#pragma unroll
            for (int kk = 0; kk < 16; kk++) {
                float4 a = *(const float4*)&As[kk][ty * 4];
                float4 bb = *(const float4*)&Bs[kk][tx * 4];
                float ar[4] = {a.x, a.y, a.z, a.w};
                float br[4] = {bb.x, bb.y, bb.z, bb.w};
#pragma unroll
                for (int i = 0; i < 4; i++)
#pragma unroll
                    for (int j = 0; j < 4; j++) acc[i][j] += ar[i] * br[j];
            }
            __syncthreads();
        }
        float* dst = g_w1p + (size_t)z * (384 * 384);
#pragma unroll
        for (int i = 0; i < 4; i++)
#pragma unroll
            for (int j = 0; j < 4; j++)
                dst[(size_t)(m0 + ty * 4 + i) * 384 + n0 + tx * 4 + j] = acc[i][j];
    } else if (b < B_R5) {
        int j = (b - B_BC) * 256 + t;
        if (j < 384) {
            float s = 0.f;
            for (int k = 0; k < 384; k++) s += fc1_b[k] * gat1_w[k * 384 + j];
            g_b1c[j] = s;
        }
    } else if (b < B_RG) {
        int i = (b - B_R5) * 256 + t;
        g_w5r[i] = __uint_as_float(f2tf32(fc5_w[i]));
    } else if (b < B_R2) {
        int i = (b - B_RG) * 256 + t;
        g_wg2r[i] = __uint_as_float(f2tf32(gat2_w[i]));
    } else if (b < B_DEG) {
        int i = (b - B_R2) * 256 + t;
        g_w2r[i] = __uint_as_float(f2tf32(fc2_w[i]));
    } else {
        // ---- degree count + last-block exclusive scan ----
        int e = (b - B_DEG) * 256 + t;
        if (e < EA) {
            int s, d;
            edge_sd(ei, e, s, d);
            atomicAdd(&g_deg[d], 1);
        }
        __threadfence();
        __syncthreads();
        __shared__ bool isLast;
        if (t == 0) isLast = (atomicAdd(&g_ctr[0], 1) == NB_DEG - 1);
        __syncthreads();
        if (isLast) {
            __threadfence();
            __shared__ int sums[256];
            const int CH = 40;
            int vals[CH];
            int base = t * CH;
            int local = 0;
#pragma unroll
            for (int i = 0; i < CH; i++) {
                int idx = base + i;
                int v = (idx < NN) ? g_deg[idx] : 0;
                vals[i] = v;
                local += v;
            }
            sums[t] = local;
            __syncthreads();
            for (int off = 1; off < 256; off <<= 1) {
                int v = (t >= off) ? sums[t - off] : 0;
                __syncthreads();
                sums[t] += v;
                __syncthreads();
            }
            int prefix = (t == 0) ? 0 : sums[t - 1];
#pragma unroll
            for (int i = 0; i < CH; i++) {
                int idx = base + i;
                if (idx < NN) { g_off[idx] = prefix; prefix += vals[i]; }
            }
            if (t == 255) g_off[NN] = sums[255];
            for (int i = t; i < NN; i += 256) g_pos[i] = 0;
        }
    }
}

// fillk: CSR fill + piggyback sum-partials + tf32 round of w1c
#define NB_FILL 665
#define NB_RW1 576
__global__ void fillk(const int* __restrict__ ei) {
    int b = blockIdx.x, t = threadIdx.x;
    if (b < NB_FILL) {
        int e = b * 256 + t;
        if (e >= EA) return;
        int s, d;
        edge_sd(ei, e, s, d);
        int slot = atomicAdd(&g_pos[d], 1);
        g_srcl[g_off[d] + slot] = s;
    } else {
        int i = (b - NB_FILL) * 256 + t;   // exactly 384*384
        float s = g_w1p[i] + g_w1p[147456 + i] + g_w1p[294912 + i] + g_w1p[442368 + i];
        g_w1c[i] = __uint_as_float(f2tf32(s));
    }
}

// ---------------- pipelined TF32 GEMM + fused coef epilogue -------------------
// coefH: 0 = none, 8 = gat1 (8 heads x 48ch), 1 = gat2 (1 head x 256ch).
// Epilogue computes per-row head dot-products of the OUTPUT with asw/adw and
// atomicAdds into oas/oad (zero-initialized in setupA). 8-col warp groups are
// head-aligned because 48 % 8 == 0.
#define AS_W (128 * 36)    // 4608 words
#define BS_W (32 * 136)    // 4352 words
#define GEMM_SMEM ((AS_W + 2 * BS_W) * 4)   // 53248 B

__global__ void __launch_bounds__(256, 2) gemm_cp(
    const float* __restrict__ A, const uint32_t* __restrict__ B,
    const float* __restrict__ bias, float* __restrict__ C,
    int M, int K, int Nc, int coefH,
    const float* __restrict__ asw, const float* __restrict__ adw,
    float* __restrict__ oas, float* __restrict__ oad)
{
    extern __shared__ uint32_t smbuf[];
    uint32_t* As = smbuf;
    const int t = threadIdx.x, lane = t & 31, wid = t >> 5;
    const int wm = (wid & 1) * 64, wn = (wid >> 1) * 32;
    const int m0 = blockIdx.y * 128, n0 = blockIdx.x * 128;
    float acc[4][4][4];
#pragma unroll
    for (int i = 0; i < 4; i++)
#pragma unroll
        for (int j = 0; j < 4; j++)
#pragma unroll
            for (int q = 0; q < 4; q++) acc[i][j][q] = 0.f;

    const int KT = K >> 5;
    const int arow = t >> 3, akc = (t & 7) * 4;
    const int bkr = t >> 5, bnc = (t & 31) * 4;

    {
        uint32_t* Bs = smbuf + AS_W;
#pragma unroll
        for (int j = 0; j < 4; j++)
            cp_async16((uint32_t)__cvta_generic_to_shared(&Bs[(bkr + 8 * j) * 136 + bnc]),
                       &B[(size_t)(bkr + 8 * j) * Nc + n0 + bnc]);
        asm volatile("cp.async.commit_group;");
    }
    float4 areg[4];
#pragma unroll
    for (int j = 0; j < 4; j++) {
        int row = arow + 32 * j;
        areg[j] = (m0 + row < M) ? *(const float4*)&A[(size_t)(m0 + row) * K + akc]
                                 : make_float4(0.f, 0.f, 0.f, 0.f);
    }

    for (int kt = 0; kt < KT; kt++) {
#pragma unroll
        for (int j = 0; j < 4; j++) {
            int row = arow + 32 * j;
            As[row * 36 + akc + 0] = f2tf32(areg[j].x);
            As[row * 36 + akc + 1] = f2tf32(areg[j].y);
            As[row * 36 + akc + 2] = f2tf32(areg[j].z);
            As[row * 36 + akc + 3] = f2tf32(areg[j].w);
        }
        if (kt + 1 < KT) {
            uint32_t* Bs = smbuf + AS_W + ((kt + 1) & 1) * BS_W;
            int kb = (kt + 1) << 5;
#pragma unroll
            for (int j = 0; j < 4; j++)
                cp_async16((uint32_t)__cvta_generic_to_shared(&Bs[(bkr + 8 * j) * 136 + bnc]),
                           &B[(size_t)(kb + bkr + 8 * j) * Nc + n0 + bnc]);
        }
        asm volatile("cp.async.commit_group;");
        if (kt + 1 < KT) {
            int kb = (kt + 1) << 5;
#pragma unroll
            for (int j = 0; j < 4; j++) {
                int row = arow + 32 * j;
                areg[j] = (m0 + row < M)
                          ? *(const float4*)&A[(size_t)(m0 + row) * K + kb + akc]
                          : make_float4(0.f, 0.f, 0.f, 0.f);
            }
        }
        asm volatile("cp.async.wait_group 1;");
        __syncthreads();

        const uint32_t* Bs = smbuf + AS_W + (kt & 1) * BS_W;
#pragma unroll
        for (int ks = 0; ks < 4; ks++) {
            uint32_t af[4][4], bf[4][2];
            const int kk = ks * 8 + (lane & 3);
#pragma unroll
            for (int mt = 0; mt < 4; mt++) {
                int m = wm + mt * 16 + (lane >> 2);
                af[mt][0] = As[m * 36 + kk];
                af[mt][1] = As[(m + 8) * 36 + kk];
                af[mt][2] = As[m * 36 + kk + 4];
                af[mt][3] = As[(m + 8) * 36 + kk + 4];
            }
#pragma unroll
            for (int nt = 0; nt < 4; nt++) {
                int n = wn + nt * 8 + (lane >> 2);
                bf[nt][0] = Bs[kk * 136 + n];
                bf[nt][1] = Bs[(kk + 4) * 136 + n];
            }
#pragma unroll
            for (int mt = 0; mt < 4; mt++)
#pragma unroll
                for (int nt = 0; nt < 4; nt++) {
                    asm volatile(
                        "mma.sync.aligned.m16n8k8.row.col.f32.tf32.tf32.f32 "
                        "{%0,%1,%2,%3}, {%4,%5,%6,%7}, {%8,%9}, {%0,%1,%2,%3};\n"
                        : "+f"(acc[mt][nt][0]), "+f"(acc[mt][nt][1]),
                          "+f"(acc[mt][nt][2]), "+f"(acc[mt][nt][3])
                        : "r"(af[mt][0]), "r"(af[mt][1]), "r"(af[mt][2]), "r"(af[mt][3]),
                          "r"(bf[nt][0]), "r"(bf[nt][1]));
                }
        }
        __syncthreads();
    }

    const int fc = lane & 3;
#pragma unroll
    for (int mt = 0; mt < 4; mt++) {
#pragma unroll
        for (int nt = 0; nt < 4; nt++) {
            int r = m0 + wm + mt * 16 + (lane >> 2);
            int c = n0 + wn + nt * 8 + 2 * fc;
            float b0 = bias ? bias[c] : 0.f;
            float b1 = bias ? bias[c + 1] : 0.f;
            float v0 = acc[mt][nt][0] + b0, v1 = acc[mt][nt][1] + b1;
            float v2 = acc[mt][nt][2] + b0, v3 = acc[mt][nt][3] + b1;
            if (r < M) *(float2*)&C[(size_t)r * Nc + c] = make_float2(v0, v1);
            if (r + 8 < M) *(float2*)&C[(size_t)(r + 8) * Nc + c] = make_float2(v2, v3);
            if (coefH) {
                float aw0 = asw[c], aw1 = asw[c + 1];
                float dw0 = adw[c], dw1 = adw[c + 1];
                float sLo = v0 * aw0 + v1 * aw1, dLo = v0 * dw0 + v1 * dw1;
                float sHi = v2 * aw0 + v3 * aw1, dHi = v2 * dw0 + v3 * dw1;
                sLo += __shfl_xor_sync(0xffffffffu, sLo, 1);
                sLo += __shfl_xor_sync(0xffffffffu, sLo, 2);
                dLo += __shfl_xor_sync(0xffffffffu, dLo, 1);
                dLo += __shfl_xor_sync(0xffffffffu, dLo, 2);
                sHi += __shfl_xor_sync(0xffffffffu, sHi, 1);
                sHi += __shfl_xor_sync(0xffffffffu, sHi, 2);
                dHi += __shfl_xor_sync(0xffffffffu, dHi, 1);
                dHi += __shfl_xor_sync(0xffffffffu, dHi, 2);
                if (fc == 0) {
                    int hd = (coefH == 8) ? (c / 48) : 0;
                    if (r < M) {
                        atomicAdd(&oas[r * coefH + hd], sLo);
                        atomicAdd(&oad[r * coefH + hd], dLo);
                    }
                    if (r + 8 < M) {
                        atomicAdd(&oas[(r + 8) * coefH + hd], sHi);
                        atomicAdd(&oad[(r + 8) * coefH + hd], dHi);
                    }
                }
            }
        }
    }
}

// ---------------- GEMM with fused BN+residual+relu A-staging ------------------
#define RS_W (128 * 32)
#define GEMM_BN_SMEM ((AS_W + 2 * BS_W + 2 * RS_W) * 4)   // 86016 B

__global__ void __launch_bounds__(256, 2) gemm_bn(
    const float* __restrict__ G, const float* __restrict__ R,
    const float2* __restrict__ cc, const uint32_t* __restrict__ B,
    const float* __restrict__ bias, float* __restrict__ C,
    int M, int K, int Nc)
{
    extern __shared__ uint32_t smbuf[];
    uint32_t* As = smbuf;
    float* Rs0 = (float*)(smbuf + AS_W + 2 * BS_W);
    const int t = threadIdx.x, lane = t & 31, wid = t >> 5;
    const int wm = (wid & 1) * 64, wn = (wid >> 1) * 32;
    const int m0 = blockIdx.y * 128, n0 = blockIdx.x * 128;
    float acc[4][4][4];
#pragma unroll
    for (int i = 0; i < 4; i++)
#pragma unroll
        for (int j = 0; j < 4; j++)
#pragma unroll
            for (int q = 0; q < 4; q++) acc[i][j][q] = 0.f;

    const int KT = K >> 5;
    const int arow = t >> 3, akc = (t & 7) * 4;
    const int bkr = t >> 5, bnc = (t & 31) * 4;

    {
        uint32_t* Bs = smbuf + AS_W;
#pragma unroll
        for (int j = 0; j < 4; j++)
            cp_async16((uint32_t)__cvta_generic_to_shared(&Bs[(bkr + 8 * j) * 136 + bnc]),
                       &B[(size_t)(bkr + 8 * j) * Nc + n0 + bnc]);
#pragma unroll
        for (int j = 0; j < 4; j++) {
            int row = arow + 32 * j;
            int gr = m0 + row;
            int ok = (gr < M) ? 16 : 0;
            int grc = (gr < M) ? gr : (M - 1);
            cp_async16z((uint32_t)__cvta_generic_to_shared(&Rs0[row * 32 + akc]),
                        &R[(size_t)grc * K + akc], ok);
        }
        asm volatile("cp.async.commit_group;");
    }
    float4 areg[4], ccr0, ccr1;
#pragma unroll
    for (int j = 0; j < 4; j++) {
        int row = arow + 32 * j;
        areg[j] = (m0 + row < M) ? *(const float4*)&G[(size_t)(m0 + row) * K + akc]
                                 : make_float4(0.f, 0.f, 0.f, 0.f);
    }
    ccr0 = *(const float4*)&cc[akc];
    ccr1 = *(const float4*)&cc[akc + 2];

    for (int kt = 0; kt < KT; kt++) {
        asm volatile("cp.async.wait_group 0;");
        const float* Rs = Rs0 + (kt & 1) * RS_W;
#pragma unroll
        for (int j = 0; j < 4; j++) {
            int row = arow + 32 * j;
            float4 r4 = *(const float4*)&Rs[row * 32 + akc];
            float v0 = fmaxf(r4.x + (areg[j].x * ccr0.x + ccr0.y), 0.f);
            float v1 = fmaxf(r4.y + (areg[j].y * ccr0.z + ccr0.w), 0.f);
            float v2 = fmaxf(r4.z + (areg[j].z * ccr1.x + ccr1.y), 0.f);
            float v3 = fmaxf(r4.w + (areg[j].w * ccr1.z + ccr1.w), 0.f);
            As[row * 36 + akc + 0] = f2tf32(v0);
            As[row * 36 + akc + 1] = f2tf32(v1);
            As[row * 36 + akc + 2] = f2tf32(v2);
            As[row * 36 + akc + 3] = f2tf32(v3);
        }
        if (kt + 1 < KT) {
            uint32_t* Bs = smbuf + AS_W + ((kt + 1) & 1) * BS_W;
            float* Rn = Rs0 + ((kt + 1) & 1) * RS_W;
            int kb = (kt + 1) << 5;
#pragma unroll
            for (int j = 0; j < 4; j++)
                cp_async16((uint32_t)__cvta_generic_to_shared(&Bs[(bkr + 8 * j) * 136 + bnc]),
                           &B[(size_t)(kb + bkr + 8 * j) * Nc + n0 + bnc]);
#pragma unroll
            for (int j = 0; j < 4; j++) {
                int row = arow + 32 * j;
                int gr = m0 + row;
                int ok = (gr < M) ? 16 : 0;
                int grc = (gr < M) ? gr : (M - 1);
                cp_async16z((uint32_t)__cvta_generic_to_shared(&Rn[row * 32 + akc]),
                            &R[(size_t)grc * K + kb + akc], ok);
            }
        }
        asm volatile("cp.async.commit_group;");
        if (kt + 1 < KT) {
            int kb = (kt + 1) << 5;
#pragma unroll
            for (int j = 0; j < 4; j++) {
                int row = arow + 32 * j;
                areg[j] = (m0 + row < M)
                          ? *(const float4*)&G[(size_t)(m0 + row) * K + kb + akc]
                          : make_float4(0.f, 0.f, 0.f, 0.f);
            }
            ccr0 = *(const float4*)&cc[kb + akc];
            ccr1 = *(const float4*)&cc[kb + akc + 2];
        }
        __syncthreads();

        const uint32_t* Bs = smbuf + AS_W + (kt & 1) * BS_W;
#pragma unroll
        for (int ks = 0; ks < 4; ks++) {
            uint32_t af[4][4], bf[4][2];
            const int kk = ks * 8 + (lane & 3);
#pragma unroll
            for (int mt = 0; mt < 4; mt++) {
                int m = wm + mt * 16 + (lane >> 2);
                af[mt][0] = As[m * 36 + kk];
                af[mt][1] = As[(m + 8) * 36 + kk];
                af[mt][2] = As[m * 36 + kk + 4];
                af[mt][3] = As[(m + 8) * 36 + kk + 4];
            }
#pragma unroll
            for (int nt = 0; nt < 4; nt++) {
                int n = wn + nt * 8 + (lane >> 2);
                bf[nt][0] = Bs[kk * 136 + n];
                bf[nt][1] = Bs[(kk + 4) * 136 + n];
            }
#pragma unroll
            for (int mt = 0; mt < 4; mt++)
#pragma unroll
                for (int nt = 0; nt < 4; nt++) {
                    asm volatile(
                        "mma.sync.aligned.m16n8k8.row.col.f32.tf32.tf32.f32 "
                        "{%0,%1,%2,%3}, {%4,%5,%6,%7}, {%8,%9}, {%0,%1,%2,%3};\n"
                        : "+f"(acc[mt][nt][0]), "+f"(acc[mt][nt][1]),
                          "+f"(acc[mt][nt][2]), "+f"(acc[mt][nt][3])
                        : "r"(af[mt][0]), "r"(af[mt][1]), "r"(af[mt][2]), "r"(af[mt][3]),
                          "r"(bf[nt][0]), "r"(bf[nt][1]));
                }
        }
        __syncthreads();
    }

#pragma unroll
    for (int mt = 0; mt < 4; mt++) {
#pragma unroll
        for (int nt = 0; nt < 4; nt++) {
            int r = m0 + wm + mt * 16 + (lane >> 2);
            int c = n0 + wn + nt * 8 + 2 * (lane & 3);
            float b0 = bias ? bias[c] : 0.f;
            float b1 = bias ? bias[c + 1] : 0.f;
            if (r < M) {
                float2 v = make_float2(acc[mt][nt][0] + b0, acc[mt][nt][1] + b1);
                *(float2*)&C[(size_t)r * Nc + c] = v;
            }
            if (r + 8 < M) {
                float2 v = make_float2(acc[mt][nt][2] + b0, acc[mt][nt][3] + b1);
                *(float2*)&C[(size_t)(r + 8) * Nc + c] = v;
            }
        }
    }
}

// ---------------- CSR gather aggregation ----------------
__global__ void gath1k() {
    int w = (blockIdx.x * blockDim.x + threadIdx.x) >> 5;
    if (w >= NN) return;
    int lane = threadIdx.x & 31;
    int beg = g_off[w], end = g_off[w + 1];
    float ad = (lane < 8) ? g_ad1[w * 8 + lane] : 0.f;
    float den = 0.f;
    float4 acc[3];
#pragma unroll
    for (int i = 0; i < 3; i++) acc[i] = make_float4(0.f, 0.f, 0.f, 0.f);

    int s = g_srcl[beg];
    for (int j = beg; j < end; j++) {
        int snext = (j + 1 < end) ? g_srcl[j + 1] : 0;
        float ex = 0.f;
        if (lane < 8) {
            ex = __expf(leaky(g_as1[s * 8 + lane] + ad));
            den += ex;
        }
        const float4* hs = (const float4*)(g_h1 + (size_t)s * 384);
#pragma unroll
        for (int i = 0; i < 3; i++) {
            int c4 = lane + 32 * i;
            float a = __shfl_sync(0xffffffffu, ex, c4 / 12);
            float4 v = hs[c4];
            acc[i].x += v.x * a; acc[i].y += v.y * a;
            acc[i].z += v.z * a; acc[i].w += v.w * a;
        }
        s = snext;
    }
    float4* od = (float4*)(g_gout1 + (size_t)w * 384);
#pragma unroll
    for (int i = 0; i < 3; i++) {
        int c4 = lane + 32 * i;
        float dh = __shfl_sync(0xffffffffu, den, c4 / 12);
        float inv = 1.f / (dh + 1e-16f);
        od[c4] = make_float4(acc[i].x * inv, acc[i].y * inv, acc[i].z * inv, acc[i].w * inv);
    }
}

__global__ void gath2k() {
    int w = (blockIdx.x * blockDim.x + threadIdx.x) >> 5;
    if (w >= NN) return;
    int lane = threadIdx.x & 31;
    int beg = g_off[w], end = g_off[w + 1];
    float ad = g_ad2[w];
    float den = 0.f;
    float4 acc[2];
    acc[0] = make_float4(0.f, 0.f, 0.f, 0.f);
    acc[1] = make_float4(0.f, 0.f, 0.f, 0.f);

    int s = g_srcl[beg];
    for (int j = beg; j < end; j++) {
        int snext = (j + 1 < end) ? g_srcl[j + 1] : 0;
        float ex = __expf(leaky(g_as2[s] + ad));
        den += ex;
        const float4* hs = (const float4*)(g_h2 + (size_t)s * 256);
#pragma unroll
        for (int i = 0; i < 2; i++) {
            float4 v = hs[lane + 32 * i];
            acc[i].x += v.x * ex; acc[i].y += v.y * ex;
            acc[i].z += v.z * ex; acc[i].w += v.w * ex;
        }
        s = snext;
    }
    float inv = 1.f / (den + 1e-16f);
    float4* od = (float4*)(g_gout2 + (size_t)w * 256);
#pragma unroll
    for (int i = 0; i < 2; i++)
        od[lane + 32 * i] = make_float4(acc[i].x * inv, acc[i].y * inv,
                                        acc[i].z * inv, acc[i].w * inv);
}

// ---------------- batch norm partials + fused finalize -> {scale,shift} ------
__global__ void bnpf(const float* __restrict__ X, int C,
                     float* __restrict__ psum, float* __restrict__ pss,
                     float2* __restrict__ cc,
                     const float* __restrict__ gamma, const float* __restrict__ beta,
                     int ctr_idx) {
    int col = blockIdx.x * 32 + threadIdx.x;
    int tt = threadIdx.y * 32 + threadIdx.x;
    float s = 0.f, q = 0.f;
    for (int r = threadIdx.y + blockIdx.y * 8; r < NN; r += 8 * gridDim.y) {
        float v = X[(size_t)r * C + col];
        s += v; q += v * v;
    }
    __shared__ float sh[8][32], sh2[8][32];
    sh[threadIdx.y][threadIdx.x] = s;
    sh2[threadIdx.y][threadIdx.x] = q;
    __syncthreads();
    if (threadIdx.y == 0) {
#pragma unroll
        for (int y = 1; y < 8; y++) { s += sh[y][threadIdx.x]; q += sh2[y][threadIdx.x]; }
        psum[blockIdx.y * C + col] = s;
        pss[blockIdx.y * C + col] = q;
    }
    __threadfence();
    __syncthreads();
    __shared__ bool isLast;
    if (tt == 0)
        isLast = (atomicAdd(&g_ctr[ctr_idx], 1) == (int)(gridDim.x * gridDim.y) - 1);
    __syncthreads();
    if (isLast) {
        __threadfence();
        for (int c = tt; c < C; c += 256) {
            float ss = 0.f, qq = 0.f;
#pragma unroll
            for (int y = 0; y < 16; y++) { ss += psum[y * C + c]; qq += pss[y * C + c]; }
            float m = ss * (1.f / NN);
            float v = qq * (1.f / NN) - m * m;
            float sc = rsqrtf(v + 1e-5f) * gamma[c];
            cc[c] = make_float2(sc, beta[c] - m * sc);
        }
    }
}

// ---------------- pair head (float4 loads) ----------------
__global__ void pairk(const int* __restrict__ ei, const int* __restrict__ tid,
                      const float* __restrict__ w4, const float* __restrict__ b4,
                      float* __restrict__ out) {
    int gw = (blockIdx.x * blockDim.x + threadIdx.x) >> 5;
    if (gw >= TEN) return;
    int lane = threadIdx.x & 31;
    int e = tid[gw];
    int s = ei[e], d = ei[EE + e];
    const float4* hs = (const float4*)(g_hf + (size_t)s * 256);
    const float4* hd = (const float4*)(g_hf + (size_t)d * 256);
    float acc[7] = {};
#pragma unroll
    for (int k = 0; k < 2; k++) {
        int c4 = lane + 32 * k;
        float4 a = hs[c4], b = hd[c4];
        float p[4] = {a.x * b.x, a.y * b.y, a.z * b.z, a.w * b.w};
        int cb = c4 * 4;
#pragma unroll
        for (int ee = 0; ee < 4; ee++) {
            const float* wr = &w4[(cb + ee) * 7];
#pragma unroll
            for (int j = 0; j < 7; j++) acc[j] += p[ee] * wr[j];
        }
    }
#pragma unroll
    for (int j = 0; j < 7; j++)
#pragma unroll
        for (int off = 16; off; off >>= 1)
            acc[j] += __shfl_down_sync(0xffffffffu, acc[j], off);
    if (lane == 0) {
#pragma unroll
        for (int j = 0; j < 7; j++) out[(size_t)gw * 7 + j] = acc[j] + b4[j];
    }
}

// ---------------- launch ----------------
extern "C" void kernel_launch(void* const* d_in, const int* in_sizes, int n_in,
                              void* d_out, int out_size) {
    const float* x       = (const float*)d_in[0];
    const int*   ei      = (const int*)d_in[1];
    const int*   teid    = (const int*)d_in[2];
    const float* fc1_w   = (const float*)d_in[3];
    const float* fc1_b   = (const float*)d_in[4];
    const float* fc5_w   = (const float*)d_in[5];
    const float* fc5_b   = (const float*)d_in[6];
    const float* fc2_w   = (const float*)d_in[7];
    const float* fc2_b   = (const float*)d_in[8];
    const float* fc4_w   = (const float*)d_in[9];
    const float* fc4_b   = (const float*)d_in[10];
    const float* gat1_w  = (const float*)d_in[11];
    const float* gat1_as = (const float*)d_in[12];
    const float* gat1_ad = (const float*)d_in[13];
    /* gat1_b unused: BN-invariant */
    const float* gat2_w  = (const float*)d_in[15];
    const float* gat2_as = (const float*)d_in[16];
    const float* gat2_ad = (const float*)d_in[17];
    /* gat2_b unused: BN-invariant */
    const float* bn1_g   = (const float*)d_in[19];
    const float* bn1_b   = (const float*)d_in[20];
    const float* bn2_g   = (const float*)d_in[21];
    const float* bn2_b   = (const float*)d_in[22];
    float* out = (float*)d_out;

    float *p_w1c, *p_b1c, *p_w5r, *p_wg2r, *p_w2r;
    float *p_h1, *p_h5, *p_h2, *p_hf, *p_gout1, *p_gout2;
    float *p_psum1, *p_pss1, *p_psum2, *p_pss2;
    float *p_as1, *p_ad1, *p_as2, *p_ad2;
    float2 *p_cc1, *p_cc2;
    cudaGetSymbolAddress((void**)&p_w1c, g_w1c);
    cudaGetSymbolAddress((void**)&p_b1c, g_b1c);
    cudaGetSymbolAddress((void**)&p_w5r, g_w5r);
    cudaGetSymbolAddress((void**)&p_wg2r, g_wg2r);
    cudaGetSymbolAddress((void**)&p_w2r, g_w2r);
    cudaGetSymbolAddress((void**)&p_h1, g_h1);
    cudaGetSymbolAddress((void**)&p_h5, g_h5);
    cudaGetSymbolAddress((void**)&p_h2, g_h2);
    cudaGetSymbolAddress((void**)&p_hf, g_hf);
    cudaGetSymbolAddress((void**)&p_gout1, g_gout1);
    cudaGetSymbolAddress((void**)&p_gout2, g_gout2);
    cudaGetSymbolAddress((void**)&p_psum1, g_psum1);
    cudaGetSymbolAddress((void**)&p_pss1, g_pss1);
    cudaGetSymbolAddress((void**)&p_psum2, g_psum2);
    cudaGetSymbolAddress((void**)&p_pss2, g_pss2);
    cudaGetSymbolAddress((void**)&p_as1, g_as1);
    cudaGetSymbolAddress((void**)&p_ad1, g_ad1);
    cudaGetSymbolAddress((void**)&p_as2, g_as2);
    cudaGetSymbolAddress((void**)&p_ad2, g_ad2);
    cudaGetSymbolAddress((void**)&p_cc1, g_cc1);
    cudaGetSymbolAddress((void**)&p_cc2, g_cc2);

    cudaFuncSetAttribute(gemm_cp, cudaFuncAttributeMaxDynamicSharedMemorySize, GEMM_SMEM);
    cudaFuncSetAttribute(gemm_bn, cudaFuncAttributeMaxDynamicSharedMemorySize, GEMM_BN_SMEM);

    const int MB = (NN + 127) / 128;  // 79

    setupA<<<(NN * 8 + 255) / 256, 256>>>();
    setupB<<<NB_ALL, 256>>>(fc1_w, gat1_w, fc1_b, fc5_w, gat2_w, fc2_w, ei);
    fillk<<<NB_FILL + NB_RW1, 256>>>(ei);

    // h1 = x @ w1c + b1c   (+ fused gat1 coefficients)
    gemm_cp<<<dim3(3, MB), 256, GEMM_SMEM>>>(
        x, (const uint32_t*)p_w1c, p_b1c, p_h1, NN, 384, 384,
        8, gat1_as, gat1_ad, p_as1, p_ad1);

    gath1k<<<(NN * 32 + 255) / 256, 256>>>();

    bnpf<<<dim3(12, 16), dim3(32, 8)>>>(p_gout1, 384, p_psum1, p_pss1,
                                        p_cc1, bn1_g, bn1_b, 1);

    // h5 = relu(x + bn(gout1)) @ fc5_w + fc5_b
    gemm_bn<<<dim3(2, MB), 256, GEMM_BN_SMEM>>>(
        p_gout1, x, p_cc1, (const uint32_t*)p_w5r, fc5_b, p_h5, NN, 384, 256);
    // h2 = h5 @ gat2_w   (+ fused gat2 coefficients)
    gemm_cp<<<dim3(2, MB), 256, GEMM_SMEM>>>(
        p_h5, (const uint32_t*)p_wg2r, nullptr, p_h2, NN, 256, 256,
        1, gat2_as, gat2_ad, p_as2, p_ad2);

    gath2k<<<(NN * 32 + 255) / 256, 256>>>();

    bnpf<<<dim3(8, 16), dim3(32, 8)>>>(p_gout2, 256, p_psum2, p_pss2,
                                       p_cc2, bn2_g, bn2_b, 2);

    // hf = relu(h5 + bn(gout2)) @ fc2_w + fc2_b
    gemm_bn<<<dim3(2, MB), 256, GEMM_BN_SMEM>>>(
        p_gout2, p_h5, p_cc2, (const uint32_t*)p_w2r, fc2_b, p_hf, NN, 256, 256);

    pairk<<<(TEN * 32 + 255) / 256, 256>>>(ei, teid, fc4_w, fc4_b, out);
}

// round 13
// speedup vs baseline: 1.0022x; 1.0022x over previous
#include <cuda_runtime.h>
#include <cuda_bf16.h>
#include <cstdint>

#define NN 10000
#define EE 160000
#define TEN 65536
#define EA (EE + NN)   // edges + self loops = 170000

// ---------------- scratch (static device globals; no allocation) ----------------
__device__ float g_w1p[4 * 384 * 384]; // split-K partials of fc1_w @ gat1_w
__device__ float g_w1c[384 * 384];     // summed + tf32-rounded (by fillk)
__device__ float g_b1c[384];           // fc1_b @ gat1_w
__device__ float g_w5r[384 * 256];     // tf32-rounded fc5_w
__device__ float g_wg2r[256 * 256];    // tf32-rounded gat2_w
__device__ float g_w2r[256 * 256];     // tf32-rounded fc2_w
__device__ float g_h1[NN * 384];
__device__ float g_gout1[NN * 384];
__device__ float g_h5[NN * 256];
__device__ float g_h2[NN * 256];
__device__ float g_gout2[NN * 256];
__device__ float g_hf[NN * 256];

__device__ float g_as1[NN * 8], g_ad1[NN * 8];
__device__ float g_as2[NN], g_ad2[NN];
__device__ float g_psum1[16 * 384], g_pss1[16 * 384];
__device__ float g_psum2[16 * 256], g_pss2[16 * 256];
__device__ float2 g_cc1[384], g_cc2[256];   // {scale, shift} per column

// CSR by destination (shared by both GAT layers)
__device__ int g_deg[NN];
__device__ int g_off[NN + 1];
__device__ int g_pos[NN];
__device__ int g_srcl[EA];
__device__ int g_ctr[3];   // [0]=degk cnt, [1]/[2]=bnpf cnt

// ---------------- helpers ----------------
__device__ __forceinline__ void edge_sd(const int* __restrict__ ei, int e, int& s, int& d) {
    if (e < EE) { s = ei[e]; d = ei[EE + e]; }
    else        { s = e - EE; d = e - EE; }
}

__device__ __forceinline__ float leaky(float v) { return v > 0.f ? v : 0.2f * v; }

__device__ __forceinline__ uint32_t f2tf32(float v) {
    uint32_t u;
    asm("cvt.rna.tf32.f32 %0, %1;" : "=r"(u) : "f"(v));
    return u;
}

__device__ __forceinline__ void cp_async16(uint32_t dst_s, const void* src) {
    asm volatile("cp.async.cg.shared.global [%0], [%1], 16;\n" :: "r"(dst_s), "l"(src));
}
__device__ __forceinline__ void cp_async16z(uint32_t dst_s, const void* src, int sz) {
    asm volatile("cp.async.cg.shared.global [%0], [%1], 16, %2;\n"
                 :: "r"(dst_s), "l"(src), "r"(sz));
}

// ---------------- setupA: zero degree counters ----------------
__global__ void setupA() {
    int i = blockIdx.x * blockDim.x + threadIdx.x;
    if (i < NN) g_deg[i] = 0;
    if (i < 3) g_ctr[i] = 0;
}

// ---------------- setupB: merged independent prep jobs ----------------
#define NB_G 144
#define NB_BC 2
#define NB_R5 384
#define NB_RG 256
#define NB_R2 256
#define NB_DEG 665
#define B_BC   (NB_G)
#define B_R5   (B_BC + NB_BC)
#define B_RG   (B_R5 + NB_R5)
#define B_R2   (B_RG + NB_RG)
#define B_DEG  (B_R2 + NB_R2)
#define NB_ALL (B_DEG + NB_DEG)

__global__ void __launch_bounds__(256) setupB(
    const float* __restrict__ fc1_w, const float* __restrict__ gat1_w,
    const float* __restrict__ fc1_b,
    const float* __restrict__ fc5_w, const float* __restrict__ gat2_w,
    const float* __restrict__ fc2_w, const int* __restrict__ ei)
{
    const int b = blockIdx.x;
    const int t = threadIdx.x;

    if (b < NB_G) {
        // ---- fp32 split-K 384^3 weight-fuse tile: write partial (deterministic) ----
        __shared__ float As[16][64];
        __shared__ float Bs[16][64];
        int q = b;
        int z = q & 3; q >>= 2;
        int bx = q % 6, by = q / 6;
        const int m0 = by * 64, n0 = bx * 64;
        const int kbeg = z * 96, kend = kbeg + 96;
        const int tx = t & 15, ty = t >> 4;
        const int la_m = t >> 2, la_k = (t & 3) * 4;
        const int lb_k = t >> 4, lb_n = (t & 15) * 4;
        float acc[4][4] = {};
        for (int k0 = kbeg; k0 < kend; k0 += 16) {
            float4 av = *(const float4*)&fc1_w[(size_t)(m0 + la_m) * 384 + k0 + la_k];
            As[la_k + 0][la_m] = av.x; As[la_k + 1][la_m] = av.y;
            As[la_k + 2][la_m] = av.z; As[la_k + 3][la_m] = av.w;
            *(float4*)&Bs[lb_k][lb_n] =
                *(const float4*)&gat1_w[(size_t)(k0 + lb_k) * 384 + n0 + lb_n];
            __syncthreads();
#pragma unroll
            for (int kk = 0; kk < 16; kk++) {
                float4 a = *(const float4*)&As[kk][ty * 4];
                float4 bb = *(const float4*)&Bs[kk][tx * 4];
                float ar[4] = {a.x, a.y, a.z, a.w};
                float br[4] = {bb.x, bb.y, bb.z, bb.w};
#pragma unroll
                for (int i = 0; i < 4; i++)
#pragma unroll
                    for (int j = 0; j < 4; j++) acc[i][j] += ar[i] * br[j];
            }
            __syncthreads();
        }
        float* dst = g_w1p + (size_t)z * (384 * 384);
#pragma unroll
        for (int i = 0; i < 4; i++)
#pragma unroll
            for (int j = 0; j < 4; j++)
                dst[(size_t)(m0 + ty * 4 + i) * 384 + n0 + tx * 4 + j] = acc[i][j];
    } else if (b < B_R5) {
        int j = (b - B_BC) * 256 + t;
        if (j < 384) {
            float s = 0.f;
            for (int k = 0; k < 384; k++) s += fc1_b[k] * gat1_w[k * 384 + j];
            g_b1c[j] = s;
        }
    } else if (b < B_RG) {
        int i = (b - B_R5) * 256 + t;
        g_w5r[i] = __uint_as_float(f2tf32(fc5_w[i]));
    } else if (b < B_R2) {
        int i = (b - B_RG) * 256 + t;
        g_wg2r[i] = __uint_as_float(f2tf32(gat2_w[i]));
    } else if (b < B_DEG) {
        int i = (b - B_R2) * 256 + t;
        g_w2r[i] = __uint_as_float(f2tf32(fc2_w[i]));
    } else {
        // ---- degree count + last-block exclusive scan ----
        int e = (b - B_DEG) * 256 + t;
        if (e < EA) {
            int s, d;
            edge_sd(ei, e, s, d);
            atomicAdd(&g_deg[d], 1);
        }
        __threadfence();
        __syncthreads();
        __shared__ bool isLast;
        if (t == 0) isLast = (atomicAdd(&g_ctr[0], 1) == NB_DEG - 1);
        __syncthreads();
        if (isLast) {
            __threadfence();
            __shared__ int sums[256];
            const int CH = 40;
            int vals[CH];
            int base = t * CH;
            int local = 0;
#pragma unroll
            for (int i = 0; i < CH; i++) {
                int idx = base + i;
                int v = (idx < NN) ? g_deg[idx] : 0;
                vals[i] = v;
                local += v;
            }
            sums[t] = local;
            __syncthreads();
            for (int off = 1; off < 256; off <<= 1) {
                int v = (t >= off) ? sums[t - off] : 0;
                __syncthreads();
                sums[t] += v;
                __syncthreads();
            }
            int prefix = (t == 0) ? 0 : sums[t - 1];
#pragma unroll
            for (int i = 0; i < CH; i++) {
                int idx = base + i;
                if (idx < NN) { g_off[idx] = prefix; prefix += vals[i]; }
            }
            if (t == 255) g_off[NN] = sums[255];
            for (int i = t; i < NN; i += 256) g_pos[i] = 0;
        }
    }
}

// fillk: CSR fill + piggyback sum-partials + tf32 round of w1c
#define NB_FILL 665
#define NB_RW1 576
__global__ void fillk(const int* __restrict__ ei) {
    int b = blockIdx.x, t = threadIdx.x;
    if (b < NB_FILL) {
        int e = b * 256 + t;
        if (e >= EA) return;
        int s, d;
        edge_sd(ei, e, s, d);
        int slot = atomicAdd(&g_pos[d], 1);
        g_srcl[g_off[d] + slot] = s;
    } else {
        int i = (b - NB_FILL) * 256 + t;   // exactly 384*384
        float s = g_w1p[i] + g_w1p[147456 + i] + g_w1p[294912 + i] + g_w1p[442368 + i];
        g_w1c[i] = __uint_as_float(f2tf32(s));
    }
}

// ---------------- pipelined TF32 GEMM (plain; byte-identical to R10/R11) ------
#define AS_W (128 * 36)    // 4608 words
#define BS_W (32 * 136)    // 4352 words
#define GEMM_SMEM ((AS_W + 2 * BS_W) * 4)   // 53248 B

__global__ void __launch_bounds__(256, 2) gemm_cp(
    const float* __restrict__ A, const uint32_t* __restrict__ B,
    const float* __restrict__ bias, float* __restrict__ C,
    int M, int K, int Nc)
{
    extern __shared__ uint32_t smbuf[];
    uint32_t* As = smbuf;
    const int t = threadIdx.x, lane = t & 31, wid = t >> 5;
    const int wm = (wid & 1) * 64, wn = (wid >> 1) * 32;
    const int m0 = blockIdx.y * 128, n0 = blockIdx.x * 128;
    float acc[4][4][4];
#pragma unroll
    for (int i = 0; i < 4; i++)
#pragma unroll
        for (int j = 0; j < 4; j++)
#pragma unroll
            for (int q = 0; q < 4; q++) acc[i][j][q] = 0.f;

    const int KT = K >> 5;
    const int arow = t >> 3, akc = (t & 7) * 4;
    const int bkr = t >> 5, bnc = (t & 31) * 4;

    {
        uint32_t* Bs = smbuf + AS_W;
#pragma unroll
        for (int j = 0; j < 4; j++)
            cp_async16((uint32_t)__cvta_generic_to_shared(&Bs[(bkr + 8 * j) * 136 + bnc]),
                       &B[(size_t)(bkr + 8 * j) * Nc + n0 + bnc]);
        asm volatile("cp.async.commit_group;");
    }
    float4 areg[4];
#pragma unroll
    for (int j = 0; j < 4; j++) {
        int row = arow + 32 * j;
        areg[j] = (m0 + row < M) ? *(const float4*)&A[(size_t)(m0 + row) * K + akc]
                                 : make_float4(0.f, 0.f, 0.f, 0.f);
    }

    for (int kt = 0; kt < KT; kt++) {
#pragma unroll
        for (int j = 0; j < 4; j++) {
            int row = arow + 32 * j;
            As[row * 36 + akc + 0] = f2tf32(areg[j].x);
            As[row * 36 + akc + 1] = f2tf32(areg[j].y);
            As[row * 36 + akc + 2] = f2tf32(areg[j].z);
            As[row * 36 + akc + 3] = f2tf32(areg[j].w);
        }
        if (kt + 1 < KT) {
            uint32_t* Bs = smbuf + AS_W + ((kt + 1) & 1) * BS_W;
            int kb = (kt + 1) << 5;
#pragma unroll
            for (int j = 0; j < 4; j++)
                cp_async16((uint32_t)__cvta_generic_to_shared(&Bs[(bkr + 8 * j) * 136 + bnc]),
                           &B[(size_t)(kb + bkr + 8 * j) * Nc + n0 + bnc]);
        }
        asm volatile("cp.async.commit_group;");
        if (kt + 1 < KT) {
            int kb = (kt + 1) << 5;
#pragma unroll
            for (int j = 0; j < 4; j++) {
                int row = arow + 32 * j;
                areg[j] = (m0 + row < M)
                          ? *(const float4*)&A[(size_t)(m0 + row) * K + kb + akc]
                          : make_float4(0.f, 0.f, 0.f, 0.f);
            }
        }
        asm volatile("cp.async.wait_group 1;");
        __syncthreads();

        const uint32_t* Bs = smbuf + AS_W + (kt & 1) * BS_W;
#pragma unroll
        for (int ks = 0; ks < 4; ks++) {
            uint32_t af[4][4], bf[4][2];
            const int kk = ks * 8 + (lane & 3);
#pragma unroll
            for (int mt = 0; mt < 4; mt++) {
                int m = wm + mt * 16 + (lane >> 2);
                af[mt][0] = As[m * 36 + kk];
                af[mt][1] = As[(m + 8) * 36 + kk];
                af[mt][2] = As[m * 36 + kk + 4];
                af[mt][3] = As[(m + 8) * 36 + kk + 4];
            }
#pragma unroll
            for (int nt = 0; nt < 4; nt++) {
                int n = wn + nt * 8 + (lane >> 2);
                bf[nt][0] = Bs[kk * 136 + n];
                bf[nt][1] = Bs[(kk + 4) * 136 + n];
            }
#pragma unroll
            for (int mt = 0; mt < 4; mt++)
#pragma unroll
                for (int nt = 0; nt < 4; nt++) {
                    asm volatile(
                        "mma.sync.aligned.m16n8k8.row.col.f32.tf32.tf32.f32 "
                        "{%0,%1,%2,%3}, {%4,%5,%6,%7}, {%8,%9}, {%0,%1,%2,%3};\n"
                        : "+f"(acc[mt][nt][0]), "+f"(acc[mt][nt][1]),
                          "+f"(acc[mt][nt][2]), "+f"(acc[mt][nt][3])
                        : "r"(af[mt][0]), "r"(af[mt][1]), "r"(af[mt][2]), "r"(af[mt][3]),
                          "r"(bf[nt][0]), "r"(bf[nt][1]));
                }
        }
        __syncthreads();
    }

#pragma unroll
    for (int mt = 0; mt < 4; mt++) {
#pragma unroll
        for (int nt = 0; nt < 4; nt++) {
            int r = m0 + wm + mt * 16 + (lane >> 2);
            int c = n0 + wn + nt * 8 + 2 * (lane & 3);
            float b0 = bias ? bias[c] : 0.f;
            float b1 = bias ? bias[c + 1] : 0.f;
            if (r < M) {
                float2 v = make_float2(acc[mt][nt][0] + b0, acc[mt][nt][1] + b1);
                *(float2*)&C[(size_t)r * Nc + c] = v;
            }
            if (r + 8 < M) {
                float2 v = make_float2(acc[mt][nt][2] + b0, acc[mt][nt][3] + b1);
                *(float2*)&C[(size_t)(r + 8) * Nc + c] = v;
            }
        }
    }
}

// ---------------- GEMM with fused BN+residual+relu A-staging ------------------
#define RS_W (128 * 32)
#define GEMM_BN_SMEM ((AS_W + 2 * BS_W + 2 * RS_W) * 4)   // 86016 B

__global__ void __launch_bounds__(256, 2) gemm_bn(
    const float* __restrict__ G, const float* __restrict__ R,
    const float2* __restrict__ cc, const uint32_t* __restrict__ B,
    const float* __restrict__ bias, float* __restrict__ C,
    int M, int K, int Nc)
{
    extern __shared__ uint32_t smbuf[];
    uint32_t* As = smbuf;
    float* Rs0 = (float*)(smbuf + AS_W + 2 * BS_W);
    const int t = threadIdx.x, lane = t & 31, wid = t >> 5;
    const int wm = (wid & 1) * 64, wn = (wid >> 1) * 32;
    const int m0 = blockIdx.y * 128, n0 = blockIdx.x * 128;
    float acc[4][4][4];
#pragma unroll
    for (int i = 0; i < 4; i++)
#pragma unroll
        for (int j = 0; j < 4; j++)
#pragma unroll
            for (int q = 0; q < 4; q++) acc[i][j][q] = 0.f;

    const int KT = K >> 5;
    const int arow = t >> 3, akc = (t & 7) * 4;
    const int bkr = t >> 5, bnc = (t & 31) * 4;

    {
        uint32_t* Bs = smbuf + AS_W;
#pragma unroll
        for (int j = 0; j < 4; j++)
            cp_async16((uint32_t)__cvta_generic_to_shared(&Bs[(bkr + 8 * j) * 136 + bnc]),
                       &B[(size_t)(bkr + 8 * j) * Nc + n0 + bnc]);
#pragma unroll
        for (int j = 0; j < 4; j++) {
            int row = arow + 32 * j;
            int gr = m0 + row;
            int ok = (gr < M) ? 16 : 0;
            int grc = (gr < M) ? gr : (M - 1);
            cp_async16z((uint32_t)__cvta_generic_to_shared(&Rs0[row * 32 + akc]),
                        &R[(size_t)grc * K + akc], ok);
        }
        asm volatile("cp.async.commit_group;");
    }
    float4 areg[4], ccr0, ccr1;
#pragma unroll
    for (int j = 0; j < 4; j++) {
        int row = arow + 32 * j;
        areg[j] = (m0 + row < M) ? *(const float4*)&G[(size_t)(m0 + row) * K + akc]
                                 : make_float4(0.f, 0.f, 0.f, 0.f);
    }
    ccr0 = *(const float4*)&cc[akc];
    ccr1 = *(const float4*)&cc[akc + 2];

    for (int kt = 0; kt < KT; kt++) {
        asm volatile("cp.async.wait_group 0;");
        const float* Rs = Rs0 + (kt & 1) * RS_W;
#pragma unroll
        for (int j = 0; j < 4; j++) {
            int row = arow + 32 * j;
            float4 r4 = *(const float4*)&Rs[row * 32 + akc];
            float v0 = fmaxf(r4.x + (areg[j].x * ccr0.x + ccr0.y), 0.f);
            float v1 = fmaxf(r4.y + (areg[j].y * ccr0.z + ccr0.w), 0.f);
            float v2 = fmaxf(r4.z + (areg[j].z * ccr1.x + ccr1.y), 0.f);
            float v3 = fmaxf(r4.w + (areg[j].w * ccr1.z + ccr1.w), 0.f);
            As[row * 36 + akc + 0] = f2tf32(v0);
            As[row * 36 + akc + 1] = f2tf32(v1);
            As[row * 36 + akc + 2] = f2tf32(v2);
            As[row * 36 + akc + 3] = f2tf32(v3);
        }
        if (kt + 1 < KT) {
            uint32_t* Bs = smbuf + AS_W + ((kt + 1) & 1) * BS_W;
            float* Rn = Rs0 + ((kt + 1) & 1) * RS_W;
            int kb = (kt + 1) << 5;
#pragma unroll
            for (int j = 0; j < 4; j++)
                cp_async16((uint32_t)__cvta_generic_to_shared(&Bs[(bkr + 8 * j) * 136 + bnc]),
                           &B[(size_t)(kb + bkr + 8 * j) * Nc + n0 + bnc]);
#pragma unroll
            for (int j = 0; j < 4; j++) {
                int row = arow + 32 * j;
                int gr = m0 + row;
                int ok = (gr < M) ? 16 : 0;
                int grc = (gr < M) ? gr : (M - 1);
                cp_async16z((uint32_t)__cvta_generic_to_shared(&Rn[row * 32 + akc]),
                            &R[(size_t)grc * K + kb + akc], ok);
            }
        }
        asm volatile("cp.async.commit_group;");
        if (kt + 1 < KT) {
            int kb = (kt + 1) << 5;
#pragma unroll
            for (int j = 0; j < 4; j++) {
                int row = arow + 32 * j;
                areg[j] = (m0 + row < M)
                          ? *(const float4*)&G[(size_t)(m0 + row) * K + kb + akc]
                          : make_float4(0.f, 0.f, 0.f, 0.f);
            }
            ccr0 = *(const float4*)&cc[kb + akc];
            ccr1 = *(const float4*)&cc[kb + akc + 2];
        }
        __syncthreads();

        const uint32_t* Bs = smbuf + AS_W + (kt & 1) * BS_W;
#pragma unroll
        for (int ks = 0; ks < 4; ks++) {
            uint32_t af[4][4], bf[4][2];
            const int kk = ks * 8 + (lane & 3);
#pragma unroll
            for (int mt = 0; mt < 4; mt++) {
                int m = wm + mt * 16 + (lane >> 2);
                af[mt][0] = As[m * 36 + kk];
                af[mt][1] = As[(m + 8) * 36 + kk];
                af[mt][2] = As[m * 36 + kk + 4];
                af[mt][3] = As[(m + 8) * 36 + kk + 4];
            }
#pragma unroll
            for (int nt = 0; nt < 4; nt++) {
                int n = wn + nt * 8 + (lane >> 2);
                bf[nt][0] = Bs[kk * 136 + n];
                bf[nt][1] = Bs[(kk + 4) * 136 + n];
            }
#pragma unroll
            for (int mt = 0; mt < 4; mt++)
#pragma unroll
                for (int nt = 0; nt < 4; nt++) {
                    asm volatile(
                        "mma.sync.aligned.m16n8k8.row.col.f32.tf32.tf32.f32 "
                        "{%0,%1,%2,%3}, {%4,%5,%6,%7}, {%8,%9}, {%0,%1,%2,%3};\n"
                        : "+f"(acc[mt][nt][0]), "+f"(acc[mt][nt][1]),
                          "+f"(acc[mt][nt][2]), "+f"(acc[mt][nt][3])
                        : "r"(af[mt][0]), "r"(af[mt][1]), "r"(af[mt][2]), "r"(af[mt][3]),
                          "r"(bf[nt][0]), "r"(bf[nt][1]));
                }
        }
        __syncthreads();
    }

#pragma unroll
    for (int mt = 0; mt < 4; mt++) {
#pragma unroll
        for (int nt = 0; nt < 4; nt++) {
            int r = m0 + wm + mt * 16 + (lane >> 2);
            int c = n0 + wn + nt * 8 + 2 * (lane & 3);
            float b0 = bias ? bias[c] : 0.f;
            float b1 = bias ? bias[c + 1] : 0.f;
            if (r < M) {
                float2 v = make_float2(acc[mt][nt][0] + b0, acc[mt][nt][1] + b1);
                *(float2*)&C[(size_t)r * Nc + c] = v;
            }
            if (r + 8 < M) {
                float2 v = make_float2(acc[mt][nt][2] + b0, acc[mt][nt][3] + b1);
                *(float2*)&C[(size_t)(r + 8) * Nc + c] = v;
            }
        }
    }
}

// ---------------- GAT coefficients (standalone, R11 versions) -----------------
__global__ void coef1k(const float* __restrict__ asw, const float* __restrict__ adw) {
    int w = (blockIdx.x * blockDim.x + threadIdx.x) >> 5;
    if (w >= NN) return;
    int lane = threadIdx.x & 31;
    int hd = lane >> 2;
    int l2 = lane & 3;
    const float4* hp = (const float4*)(g_h1 + (size_t)w * 384);
    const float4* ap = (const float4*)asw;
    const float4* dp = (const float4*)adw;
    float s = 0.f, d = 0.f;
#pragma unroll
    for (int i = 0; i < 3; i++) {
        int c4 = hd * 12 + l2 + 4 * i;
        float4 v = hp[c4], a = ap[c4], dd = dp[c4];
        s += v.x * a.x + v.y * a.y + v.z * a.z + v.w * a.w;
        d += v.x * dd.x + v.y * dd.y + v.z * dd.z + v.w * dd.w;
    }
    s += __shfl_xor_sync(0xffffffffu, s, 1);
    s += __shfl_xor_sync(0xffffffffu, s, 2);
    d += __shfl_xor_sync(0xffffffffu, d, 1);
    d += __shfl_xor_sync(0xffffffffu, d, 2);
    if (l2 == 0) {
        g_as1[w * 8 + hd] = s;
        g_ad1[w * 8 + hd] = d;
    }
}

__global__ void coef2k(const float* __restrict__ asw, const float* __restrict__ adw) {
    int gw = (blockIdx.x * blockDim.x + threadIdx.x) >> 5;
    if (gw >= NN) return;
    int lane = threadIdx.x & 31;
    const float* hp = g_h2 + (size_t)gw * 256;
    float s = 0.f, d = 0.f;
#pragma unroll
    for (int k = 0; k < 8; k++) {
        int c = lane + 32 * k;
        float v = hp[c];
        s += v * asw[c]; d += v * adw[c];
    }
#pragma unroll
    for (int off = 16; off; off >>= 1) {
        s += __shfl_down_sync(0xffffffffu, s, off);
        d += __shfl_down_sync(0xffffffffu, d, off);
    }
    if (lane == 0) { g_as2[gw] = s; g_ad2[gw] = d; }
}

// ---------------- CSR gather aggregation ----------------
__global__ void gath1k() {
    int w = (blockIdx.x * blockDim.x + threadIdx.x) >> 5;
    if (w >= NN) return;
    int lane = threadIdx.x & 31;
    int beg = g_off[w], end = g_off[w + 1];
    float ad = (lane < 8) ? g_ad1[w * 8 + lane] : 0.f;
    float den = 0.f;
    float4 acc[3];
#pragma unroll
    for (int i = 0; i < 3; i++) acc[i] = make_float4(0.f, 0.f, 0.f, 0.f);

    int s = g_srcl[beg];
    for (int j = beg; j < end; j++) {
        int snext = (j + 1 < end) ? g_srcl[j + 1] : 0;
        float ex = 0.f;
        if (lane < 8) {
            ex = __expf(leaky(g_as1[s * 8 + lane] + ad));
            den += ex;
        }
        const float4* hs = (const float4*)(g_h1 + (size_t)s * 384);
#pragma unroll
        for (int i = 0; i < 3; i++) {
            int c4 = lane + 32 * i;
            float a = __shfl_sync(0xffffffffu, ex, c4 / 12);
            float4 v = hs[c4];
            acc[i].x += v.x * a; acc[i].y += v.y * a;
            acc[i].z += v.z * a; acc[i].w += v.w * a;
        }
        s = snext;
    }
    float4* od = (float4*)(g_gout1 + (size_t)w * 384);
#pragma unroll
    for (int i = 0; i < 3; i++) {
        int c4 = lane + 32 * i;
        float dh = __shfl_sync(0xffffffffu, den, c4 / 12);
        float inv = 1.f / (dh + 1e-16f);
        od[c4] = make_float4(acc[i].x * inv, acc[i].y * inv, acc[i].z * inv, acc[i].w * inv);
    }
}

__global__ void gath2k() {
    int w = (blockIdx.x * blockDim.x + threadIdx.x) >> 5;
    if (w >= NN) return;
    int lane = threadIdx.x & 31;
    int beg = g_off[w], end = g_off[w + 1];
    float ad = g_ad2[w];
    float den = 0.f;
    float4 acc[2];
    acc[0] = make_float4(0.f, 0.f, 0.f, 0.f);
    acc[1] = make_float4(0.f, 0.f, 0.f, 0.f);

    int s = g_srcl[beg];
    for (int j = beg; j < end; j++) {
        int snext = (j + 1 < end) ? g_srcl[j + 1] : 0;
        float ex = __expf(leaky(g_as2[s] + ad));
        den += ex;
        const float4* hs = (const float4*)(g_h2 + (size_t)s * 256);
#pragma unroll
        for (int i = 0; i < 2; i++) {
            float4 v = hs[lane + 32 * i];
            acc[i].x += v.x * ex; acc[i].y += v.y * ex;
            acc[i].z += v.z * ex; acc[i].w += v.w * ex;
        }
        s = snext;
    }
    float inv = 1.f / (den + 1e-16f);
    float4* od = (float4*)(g_gout2 + (size_t)w * 256);
#pragma unroll
    for (int i = 0; i < 2; i++)
        od[lane + 32 * i] = make_float4(acc[i].x * inv, acc[i].y * inv,
                                        acc[i].z * inv, acc[i].w * inv);
}

// ---------------- batch norm partials + fused finalize -> {scale,shift} ------
__global__ void bnpf(const float* __restrict__ X, int C,
                     float* __restrict__ psum, float* __restrict__ pss,
                     float2* __restrict__ cc,
                     const float* __restrict__ gamma, const float* __restrict__ beta,
                     int ctr_idx) {
    int col = blockIdx.x * 32 + threadIdx.x;
    int tt = threadIdx.y * 32 + threadIdx.x;
    float s = 0.f, q = 0.f;
    for (int r = threadIdx.y + blockIdx.y * 8; r < NN; r += 8 * gridDim.y) {
        float v = X[(size_t)r * C + col];
        s += v; q += v * v;
    }
    __shared__ float sh[8][32], sh2[8][32];
    sh[threadIdx.y][threadIdx.x] = s;
    sh2[threadIdx.y][threadIdx.x] = q;
    __syncthreads();
    if (threadIdx.y == 0) {
#pragma unroll
        for (int y = 1; y < 8; y++) { s += sh[y][threadIdx.x]; q += sh2[y][threadIdx.x]; }
        psum[blockIdx.y * C + col] = s;
        pss[blockIdx.y * C + col] = q;
    }
    __threadfence();
    __syncthreads();
    __shared__ bool isLast;
    if (tt == 0)
        isLast = (atomicAdd(&g_ctr[ctr_idx], 1) == (int)(gridDim.x * gridDim.y) - 1);
    __syncthreads();
    if (isLast) {
        __threadfence();
        for (int c = tt; c < C; c += 256) {
            float ss = 0.f, qq = 0.f;
#pragma unroll
            for (int y = 0; y < 16; y++) { ss += psum[y * C + c]; qq += pss[y * C + c]; }
            float m = ss * (1.f / NN);
            float v = qq * (1.f / NN) - m * m;
            float sc = rsqrtf(v + 1e-5f) * gamma[c];
            cc[c] = make_float2(sc, beta[c] - m * sc);
        }
    }
}

// ---------------- pair head (float4 loads) ----------------
__global__ void pairk(const int* __restrict__ ei, const int* __restrict__ tid,
                      const float* __restrict__ w4, const float* __restrict__ b4,
                      float* __restrict__ out) {
    int gw = (blockIdx.x * blockDim.x + threadIdx.x) >> 5;
    if (gw >= TEN) return;
    int lane = threadIdx.x & 31;
    int e = tid[gw];
    int s = ei[e], d = ei[EE + e];
    const float4* hs = (const float4*)(g_hf + (size_t)s * 256);
    const float4* hd = (const float4*)(g_hf + (size_t)d * 256);
    float acc[7] = {};
#pragma unroll
    for (int k = 0; k < 2; k++) {
        int c4 = lane + 32 * k;
        float4 a = hs[c4], b = hd[c4];
        float p[4] = {a.x * b.x, a.y * b.y, a.z * b.z, a.w * b.w};
        int cb = c4 * 4;
#pragma unroll
        for (int ee = 0; ee < 4; ee++) {
            const float* wr = &w4[(cb + ee) * 7];
#pragma unroll
            for (int j = 0; j < 7; j++) acc[j] += p[ee] * wr[j];
        }
    }
#pragma unroll
    for (int j = 0; j < 7; j++)
#pragma unroll
        for (int off = 16; off; off >>= 1)
            acc[j] += __shfl_down_sync(0xffffffffu, acc[j], off);
    if (lane == 0) {
#pragma unroll
        for (int j = 0; j < 7; j++) out[(size_t)gw * 7 + j] = acc[j] + b4[j];
    }
}

// ---------------- launch ----------------
extern "C" void kernel_launch(void* const* d_in, const int* in_sizes, int n_in,
                              void* d_out, int out_size) {
    const float* x       = (const float*)d_in[0];
    const int*   ei      = (const int*)d_in[1];
    const int*   teid    = (const int*)d_in[2];
    const float* fc1_w   = (const float*)d_in[3];
    const float* fc1_b   = (const float*)d_in[4];
    const float* fc5_w   = (const float*)d_in[5];
    const float* fc5_b   = (const float*)d_in[6];
    const float* fc2_w   = (const float*)d_in[7];
    const float* fc2_b   = (const float*)d_in[8];
    const float* fc4_w   = (const float*)d_in[9];
    const float* fc4_b   = (const float*)d_in[10];
    const float* gat1_w  = (const float*)d_in[11];
    const float* gat1_as = (const float*)d_in[12];
    const float* gat1_ad = (const float*)d_in[13];
    /* gat1_b unused: BN-invariant */
    const float* gat2_w  = (const float*)d_in[15];
    const float* gat2_as = (const float*)d_in[16];
    const float* gat2_ad = (const float*)d_in[17];
    /* gat2_b unused: BN-invariant */
    const float* bn1_g   = (const float*)d_in[19];
    const float* bn1_b   = (const float*)d_in[20];
    const float* bn2_g   = (const float*)d_in[21];
    const float* bn2_b   = (const float*)d_in[22];
    float* out = (float*)d_out;

    float *p_w1c, *p_b1c, *p_w5r, *p_wg2r, *p_w2r;
    float *p_h1, *p_h5, *p_h2, *p_hf, *p_gout1, *p_gout2;
    float *p_psum1, *p_pss1, *p_psum2, *p_pss2;
    float2 *p_cc1, *p_cc2;
    cudaGetSymbolAddress((void**)&p_w1c, g_w1c);
    cudaGetSymbolAddress((void**)&p_b1c, g_b1c);
    cudaGetSymbolAddress((void**)&p_w5r, g_w5r);
    cudaGetSymbolAddress((void**)&p_wg2r, g_wg2r);
    cudaGetSymbolAddress((void**)&p_w2r, g_w2r);
    cudaGetSymbolAddress((void**)&p_h1, g_h1);
    cudaGetSymbolAddress((void**)&p_h5, g_h5);
    cudaGetSymbolAddress((void**)&p_h2, g_h2);
    cudaGetSymbolAddress((void**)&p_hf, g_hf);
    cudaGetSymbolAddress((void**)&p_gout1, g_gout1);
    cudaGetSymbolAddress((void**)&p_gout2, g_gout2);
    cudaGetSymbolAddress((void**)&p_psum1, g_psum1);
    cudaGetSymbolAddress((void**)&p_pss1, g_pss1);
    cudaGetSymbolAddress((void**)&p_psum2, g_psum2);
    cudaGetSymbolAddress((void**)&p_pss2, g_pss2);
    cudaGetSymbolAddress((void**)&p_cc1, g_cc1);
    cudaGetSymbolAddress((void**)&p_cc2, g_cc2);

    cudaFuncSetAttribute(gemm_cp, cudaFuncAttributeMaxDynamicSharedMemorySize, GEMM_SMEM);
    cudaFuncSetAttribute(gemm_bn, cudaFuncAttributeMaxDynamicSharedMemorySize, GEMM_BN_SMEM);

    const int MB = (NN + 127) / 128;  // 79

    setupA<<<40, 256>>>();
    setupB<<<NB_ALL, 256>>>(fc1_w, gat1_w, fc1_b, fc5_w, gat2_w, fc2_w, ei);
    fillk<<<NB_FILL + NB_RW1, 256>>>(ei);

    // h1 = x @ w1c + b1c
    gemm_cp<<<dim3(3, MB), 256, GEMM_SMEM>>>(
        x, (const uint32_t*)p_w1c, p_b1c, p_h1, NN, 384, 384);

    coef1k<<<(NN * 32 + 255) / 256, 256>>>(gat1_as, gat1_ad);
    gath1k<<<(NN * 32 + 255) / 256, 256>>>();

    bnpf<<<dim3(12, 16), dim3(32, 8)>>>(p_gout1, 384, p_psum1, p_pss1,
                                        p_cc1, bn1_g, bn1_b, 1);

    // h5 = relu(x + bn(gout1)) @ fc5_w + fc5_b
    gemm_bn<<<dim3(2, MB), 256, GEMM_BN_SMEM>>>(
        p_gout1, x, p_cc1, (const uint32_t*)p_w5r, fc5_b, p_h5, NN, 384, 256);
    gemm_cp<<<dim3(2, MB), 256, GEMM_SMEM>>>(
        p_h5, (const uint32_t*)p_wg2r, nullptr, p_h2, NN, 256, 256);

    coef2k<<<(NN * 32 + 255) / 256, 256>>>(gat2_as, gat2_ad);
    gath2k<<<(NN * 32 + 255) / 256, 256>>>();

    bnpf<<<dim3(8, 16), dim3(32, 8)>>>(p_gout2, 256, p_psum2, p_pss2,
                                       p_cc2, bn2_g, bn2_b, 2);

    // hf = relu(h5 + bn(gout2)) @ fc2_w + fc2_b
    gemm_bn<<<dim3(2, MB), 256, GEMM_BN_SMEM>>>(
        p_gout2, p_h5, p_cc2, (const uint32_t*)p_w2r, fc2_b, p_hf, NN, 256, 256);

    pairk<<<(TEN * 32 + 255) / 256, 256>>>(ei, teid, fc4_w, fc4_b, out);
}

// round 14
// speedup vs baseline: 1.2094x; 1.2068x over previous
#include <cuda_runtime.h>
#include <cuda_bf16.h>
#include <cstdint>

#define NN 10000
#define EE 160000
#define TEN 65536
#define EA (EE + NN)   // edges + self loops = 170000

// ---------------- scratch (static device globals; no allocation) ----------------
__device__ float g_w1p[4 * 384 * 384]; // split-K partials of fc1_w @ gat1_w
__device__ float g_w1c[384 * 384];     // summed + tf32-rounded (by fillk)
__device__ float g_b1c[384];           // fc1_b @ gat1_w
__device__ float g_w5r[384 * 256];     // tf32-rounded fc5_w
__device__ float g_wg2r[256 * 256];    // tf32-rounded gat2_w
__device__ float g_w2r[256 * 256];     // tf32-rounded fc2_w
__device__ float g_h1[NN * 384];
__device__ float g_gout1[NN * 384];
__device__ float g_h5[NN * 256];
__device__ float g_h2[NN * 256];
__device__ float g_gout2[NN * 256];
__device__ float g_hf[NN * 256];

__device__ float g_as1[NN * 8], g_ad1[NN * 8];
__device__ float g_as2[NN], g_ad2[NN];
__device__ float g_psum1[16 * 384], g_pss1[16 * 384];
__device__ float g_psum2[16 * 256], g_pss2[16 * 256];
__device__ float2 g_cc1[384], g_cc2[256];   // {scale, shift} per column

// CSR by destination (shared by both GAT layers)
__device__ int g_deg[NN];
__device__ int g_off[NN + 1];
__device__ int g_pos[NN];
__device__ int g_srcl[EA];
__device__ int g_ctr[3];   // [0]=degk cnt, [1]/[2]=bnpf cnt

// ---------------- helpers ----------------
__device__ __forceinline__ void edge_sd(const int* __restrict__ ei, int e, int& s, int& d) {
    if (e < EE) { s = ei[e]; d = ei[EE + e]; }
    else        { s = e - EE; d = e - EE; }
}

__device__ __forceinline__ float leaky(float v) { return v > 0.f ? v : 0.2f * v; }

__device__ __forceinline__ uint32_t f2tf32(float v) {
    uint32_t u;
    asm("cvt.rna.tf32.f32 %0, %1;" : "=r"(u) : "f"(v));
    return u;
}

__device__ __forceinline__ void cp_async16(uint32_t dst_s, const void* src) {
    asm volatile("cp.async.cg.shared.global [%0], [%1], 16;\n" :: "r"(dst_s), "l"(src));
}
__device__ __forceinline__ void cp_async16z(uint32_t dst_s, const void* src, int sz) {
    asm volatile("cp.async.cg.shared.global [%0], [%1], 16, %2;\n"
                 :: "r"(dst_s), "l"(src), "r"(sz));
}

// ---------------- setupA: zero degree counters ----------------
__global__ void setupA() {
    int i = blockIdx.x * blockDim.x + threadIdx.x;
    if (i < NN) g_deg[i] = 0;
    if (i < 3) g_ctr[i] = 0;
}

// ---------------- setupB: merged independent prep jobs ----------------
#define NB_G 144
#define NB_BC 2
#define NB_R5 384
#define NB_RG 256
#define NB_R2 256
#define NB_DEG 665
#define B_BC   (NB_G)
#define B_R5   (B_BC + NB_BC)
#define B_RG   (B_R5 + NB_R5)
#define B_R2   (B_RG + NB_RG)
#define B_DEG  (B_R2 + NB_R2)
#define NB_ALL (B_DEG + NB_DEG)

__global__ void __launch_bounds__(256) setupB(
    const float* __restrict__ fc1_w, const float* __restrict__ gat1_w,
    const float* __restrict__ fc1_b,
    const float* __restrict__ fc5_w, const float* __restrict__ gat2_w,
    const float* __restrict__ fc2_w, const int* __restrict__ ei)
{
    const int b = blockIdx.x;
    const int t = threadIdx.x;

    if (b < NB_G) {
        // ---- fp32 split-K 384^3 weight-fuse tile: write partial (deterministic) ----
        __shared__ float As[16][64];
        __shared__ float Bs[16][64];
        int q = b;
        int z = q & 3; q >>= 2;
        int bx = q % 6, by = q / 6;
        const int m0 = by * 64, n0 = bx * 64;
        const int kbeg = z * 96, kend = kbeg + 96;
        const int tx = t & 15, ty = t >> 4;
        const int la_m = t >> 2, la_k = (t & 3) * 4;
        const int lb_k = t >> 4, lb_n = (t & 15) * 4;
        float acc[4][4] = {};
        for (int k0 = kbeg; k0 < kend; k0 += 16) {
            float4 av = *(const float4*)&fc1_w[(size_t)(m0 + la_m) * 384 + k0 + la_k];
            As[la_k + 0][la_m] = av.x; As[la_k + 1][la_m] = av.y;
            As[la_k + 2][la_m] = av.z; As[la_k + 3][la_m] = av.w;
            *(float4*)&Bs[lb_k][lb_n] =
                *(const float4*)&gat1_w[(size_t)(k0 + lb_k) * 384 + n0 + lb_n];
            __syncthreads();
#pragma unroll
            for (int kk = 0; kk < 16; kk++) {
                float4 a = *(const float4*)&As[kk][ty * 4];
                float4 bb = *(const float4*)&Bs[kk][tx * 4];
                float ar[4] = {a.x, a.y, a.z, a.w};
                float br[4] = {bb.x, bb.y, bb.z, bb.w};
#pragma unroll
                for (int i = 0; i < 4; i++)
#pragma unroll
                    for (int j = 0; j < 4; j++) acc[i][j] += ar[i] * br[j];
            }
            __syncthreads();
        }
        float* dst = g_w1p + (size_t)z * (384 * 384);
#pragma unroll
        for (int i = 0; i < 4; i++)
#pragma unroll
            for (int j = 0; j < 4; j++)
                dst[(size_t)(m0 + ty * 4 + i) * 384 + n0 + tx * 4 + j] = acc[i][j];
    } else if (b < B_R5) {
        int j = (b - B_BC) * 256 + t;
        if (j < 384) {
            float s = 0.f;
            for (int k = 0; k < 384; k++) s += fc1_b[k] * gat1_w[k * 384 + j];
            g_b1c[j] = s;
        }
    } else if (b < B_RG) {
        int i = (b - B_R5) * 256 + t;
        g_w5r[i] = __uint_as_float(f2tf32(fc5_w[i]));
    } else if (b < B_R2) {
        int i = (b - B_RG) * 256 + t;
        g_wg2r[i] = __uint_as_float(f2tf32(gat2_w[i]));
    } else if (b < B_DEG) {
        int i = (b - B_R2) * 256 + t;
        g_w2r[i] = __uint_as_float(f2tf32(fc2_w[i]));
    } else {
        // ---- degree count + last-block exclusive scan ----
        int e = (b - B_DEG) * 256 + t;
        if (e < EA) {
            int s, d;
            edge_sd(ei, e, s, d);
            atomicAdd(&g_deg[d], 1);
        }
        __threadfence();
        __syncthreads();
        __shared__ bool isLast;
        if (t == 0) isLast = (atomicAdd(&g_ctr[0], 1) == NB_DEG - 1);
        __syncthreads();
        if (isLast) {
            __threadfence();
            __shared__ int sums[256];
            const int CH = 40;
            int vals[CH];
            int base = t * CH;
            int local = 0;
#pragma unroll
            for (int i = 0; i < CH; i++) {
                int idx = base + i;
                int v = (idx < NN) ? g_deg[idx] : 0;
                vals[i] = v;
                local += v;
            }
            sums[t] = local;
            __syncthreads();
            for (int off = 1; off < 256; off <<= 1) {
                int v = (t >= off) ? sums[t - off] : 0;
                __syncthreads();
                sums[t] += v;
                __syncthreads();
            }
            int prefix = (t == 0) ? 0 : sums[t - 1];
#pragma unroll
            for (int i = 0; i < CH; i++) {
                int idx = base + i;
                if (idx < NN) { g_off[idx] = prefix; prefix += vals[i]; }
            }
            if (t == 255) g_off[NN] = sums[255];
            for (int i = t; i < NN; i += 256) g_pos[i] = 0;
        }
    }
}

// fillk: CSR fill + piggyback sum-partials + tf32 round of w1c
#define NB_FILL 665
#define NB_RW1 576
__global__ void fillk(const int* __restrict__ ei) {
    int b = blockIdx.x, t = threadIdx.x;
    if (b < NB_FILL) {
        int e = b * 256 + t;
        if (e >= EA) return;
        int s, d;
        edge_sd(ei, e, s, d);
        int slot = atomicAdd(&g_pos[d], 1);
        g_srcl[g_off[d] + slot] = s;
    } else {
        int i = (b - NB_FILL) * 256 + t;   // exactly 384*384
        float s = g_w1p[i] + g_w1p[147456 + i] + g_w1p[294912 + i] + g_w1p[442368 + i];
        g_w1c[i] = __uint_as_float(f2tf32(s));
    }
}

// ---------------- pipelined TF32 GEMM ----------------
#define AS_W (128 * 36)    // 4608 words
#define BS_W (32 * 136)    // 4352 words
#define GEMM_SMEM ((AS_W + 2 * BS_W) * 4)   // 53248 B

__global__ void __launch_bounds__(256, 2) gemm_cp(
    const float* __restrict__ A, const uint32_t* __restrict__ B,
    const float* __restrict__ bias, float* __restrict__ C,
    int M, int K, int Nc)
{
    extern __shared__ uint32_t smbuf[];
    uint32_t* As = smbuf;
    const int t = threadIdx.x, lane = t & 31, wid = t >> 5;
    const int wm = (wid & 1) * 64, wn = (wid >> 1) * 32;
    const int m0 = blockIdx.y * 128, n0 = blockIdx.x * 128;
    float acc[4][4][4];
#pragma unroll
    for (int i = 0; i < 4; i++)
#pragma unroll
        for (int j = 0; j < 4; j++)
#pragma unroll
            for (int q = 0; q < 4; q++) acc[i][j][q] = 0.f;

    const int KT = K >> 5;
    const int arow = t >> 3, akc = (t & 7) * 4;
    const int bkr = t >> 5, bnc = (t & 31) * 4;

    {
        uint32_t* Bs = smbuf + AS_W;
#pragma unroll
        for (int j = 0; j < 4; j++)
            cp_async16((uint32_t)__cvta_generic_to_shared(&Bs[(bkr + 8 * j) * 136 + bnc]),
                       &B[(size_t)(bkr + 8 * j) * Nc + n0 + bnc]);
        asm volatile("cp.async.commit_group;");
    }
    float4 areg[4];
#pragma unroll
    for (int j = 0; j < 4; j++) {
        int row = arow + 32 * j;
        areg[j] = (m0 + row < M) ? *(const float4*)&A[(size_t)(m0 + row) * K + akc]
                                 : make_float4(0.f, 0.f, 0.f, 0.f);
    }

    for (int kt = 0; kt < KT; kt++) {
#pragma unroll
        for (int j = 0; j < 4; j++) {
            int row = arow + 32 * j;
            As[row * 36 + akc + 0] = f2tf32(areg[j].x);
            As[row * 36 + akc + 1] = f2tf32(areg[j].y);
            As[row * 36 + akc + 2] = f2tf32(areg[j].z);
            As[row * 36 + akc + 3] = f2tf32(areg[j].w);
        }
        if (kt + 1 < KT) {
            uint32_t* Bs = smbuf + AS_W + ((kt + 1) & 1) * BS_W;
            int kb = (kt + 1) << 5;
#pragma unroll
            for (int j = 0; j < 4; j++)
                cp_async16((uint32_t)__cvta_generic_to_shared(&Bs[(bkr + 8 * j) * 136 + bnc]),
                           &B[(size_t)(kb + bkr + 8 * j) * Nc + n0 + bnc]);
        }
        asm volatile("cp.async.commit_group;");
        if (kt + 1 < KT) {
            int kb = (kt + 1) << 5;
#pragma unroll
            for (int j = 0; j < 4; j++) {
                int row = arow + 32 * j;
                areg[j] = (m0 + row < M)
                          ? *(const float4*)&A[(size_t)(m0 + row) * K + kb + akc]
                          : make_float4(0.f, 0.f, 0.f, 0.f);
            }
        }
        asm volatile("cp.async.wait_group 1;");
        __syncthreads();

        const uint32_t* Bs = smbuf + AS_W + (kt & 1) * BS_W;
#pragma unroll
        for (int ks = 0; ks < 4; ks++) {
            uint32_t af[4][4], bf[4][2];
            const int kk = ks * 8 + (lane & 3);
#pragma unroll
            for (int mt = 0; mt < 4; mt++) {
                int m = wm + mt * 16 + (lane >> 2);
                af[mt][0] = As[m * 36 + kk];
                af[mt][1] = As[(m + 8) * 36 + kk];
                af[mt][2] = As[m * 36 + kk + 4];
                af[mt][3] = As[(m + 8) * 36 + kk + 4];
            }
#pragma unroll
            for (int nt = 0; nt < 4; nt++) {
                int n = wn + nt * 8 + (lane >> 2);
                bf[nt][0] = Bs[kk * 136 + n];
                bf[nt][1] = Bs[(kk + 4) * 136 + n];
            }
#pragma unroll
            for (int mt = 0; mt < 4; mt++)
#pragma unroll
                for (int nt = 0; nt < 4; nt++) {
                    asm volatile(
                        "mma.sync.aligned.m16n8k8.row.col.f32.tf32.tf32.f32 "
                        "{%0,%1,%2,%3}, {%4,%5,%6,%7}, {%8,%9}, {%0,%1,%2,%3};\n"
                        : "+f"(acc[mt][nt][0]), "+f"(acc[mt][nt][1]),
                          "+f"(acc[mt][nt][2]), "+f"(acc[mt][nt][3])
                        : "r"(af[mt][0]), "r"(af[mt][1]), "r"(af[mt][2]), "r"(af[mt][3]),
                          "r"(bf[nt][0]), "r"(bf[nt][1]));
                }
        }
        __syncthreads();
    }

#pragma unroll
    for (int mt = 0; mt < 4; mt++) {
#pragma unroll
        for (int nt = 0; nt < 4; nt++) {
            int r = m0 + wm + mt * 16 + (lane >> 2);
            int c = n0 + wn + nt * 8 + 2 * (lane & 3);
            float b0 = bias ? bias[c] : 0.f;
            float b1 = bias ? bias[c + 1] : 0.f;
            if (r < M) {
                float2 v = make_float2(acc[mt][nt][0] + b0, acc[mt][nt][1] + b1);
                *(float2*)&C[(size_t)r * Nc + c] = v;
            }
            if (r + 8 < M) {
                float2 v = make_float2(acc[mt][nt][2] + b0, acc[mt][nt][3] + b1);
                *(float2*)&C[(size_t)(r + 8) * Nc + c] = v;
            }
        }
    }
}

// ---------------- GEMM with fused BN+residual+relu A-staging ------------------
#define RS_W (128 * 32)
#define GEMM_BN_SMEM ((AS_W + 2 * BS_W + 2 * RS_W) * 4)   // 86016 B

__global__ void __launch_bounds__(256, 2) gemm_bn(
    const float* __restrict__ G, const float* __restrict__ R,
    const float2* __restrict__ cc, const uint32_t* __restrict__ B,
    const float* __restrict__ bias, float* __restrict__ C,
    int M, int K, int Nc)
{
    extern __shared__ uint32_t smbuf[];
    uint32_t* As = smbuf;
    float* Rs0 = (float*)(smbuf + AS_W + 2 * BS_W);
    const int t = threadIdx.x, lane = t & 31, wid = t >> 5;
    const int wm = (wid & 1) * 64, wn = (wid >> 1) * 32;
    const int m0 = blockIdx.y * 128, n0 = blockIdx.x * 128;
    float acc[4][4][4];
#pragma unroll
    for (int i = 0; i < 4; i++)
#pragma unroll
        for (int j = 0; j < 4; j++)
#pragma unroll
            for (int q = 0; q < 4; q++) acc[i][j][q] = 0.f;

    const int KT = K >> 5;
    const int arow = t >> 3, akc = (t & 7) * 4;
    const int bkr = t >> 5, bnc = (t & 31) * 4;

    {
        uint32_t* Bs = smbuf + AS_W;
#pragma unroll
        for (int j = 0; j < 4; j++)
            cp_async16((uint32_t)__cvta_generic_to_shared(&Bs[(bkr + 8 * j) * 136 + bnc]),
                       &B[(size_t)(bkr + 8 * j) * Nc + n0 + bnc]);
#pragma unroll
        for (int j = 0; j < 4; j++) {
            int row = arow + 32 * j;
            int gr = m0 + row;
            int ok = (gr < M) ? 16 : 0;
            int grc = (gr < M) ? gr : (M - 1);
            cp_async16z((uint32_t)__cvta_generic_to_shared(&Rs0[row * 32 + akc]),
                        &R[(size_t)grc * K + akc], ok);
        }
        asm volatile("cp.async.commit_group;");
    }
    float4 areg[4], ccr0, ccr1;
#pragma unroll
    for (int j = 0; j < 4; j++) {
        int row = arow + 32 * j;
        areg[j] = (m0 + row < M) ? *(const float4*)&G[(size_t)(m0 + row) * K + akc]
                                 : make_float4(0.f, 0.f, 0.f, 0.f);
    }
    ccr0 = *(const float4*)&cc[akc];
    ccr1 = *(const float4*)&cc[akc + 2];

    for (int kt = 0; kt < KT; kt++) {
        asm volatile("cp.async.wait_group 0;");
        const float* Rs = Rs0 + (kt & 1) * RS_W;
#pragma unroll
        for (int j = 0; j < 4; j++) {
            int row = arow + 32 * j;
            float4 r4 = *(const float4*)&Rs[row * 32 + akc];
            float v0 = fmaxf(r4.x + (areg[j].x * ccr0.x + ccr0.y), 0.f);
            float v1 = fmaxf(r4.y + (areg[j].y * ccr0.z + ccr0.w), 0.f);
            float v2 = fmaxf(r4.z + (areg[j].z * ccr1.x + ccr1.y), 0.f);
            float v3 = fmaxf(r4.w + (areg[j].w * ccr1.z + ccr1.w), 0.f);
            As[row * 36 + akc + 0] = f2tf32(v0);
            As[row * 36 + akc + 1] = f2tf32(v1);
            As[row * 36 + akc + 2] = f2tf32(v2);
            As[row * 36 + akc + 3] = f2tf32(v3);
        }
        if (kt + 1 < KT) {
            uint32_t* Bs = smbuf + AS_W + ((kt + 1) & 1) * BS_W;
            float* Rn = Rs0 + ((kt + 1) & 1) * RS_W;
            int kb = (kt + 1) << 5;
#pragma unroll
            for (int j = 0; j < 4; j++)
                cp_async16((uint32_t)__cvta_generic_to_shared(&Bs[(bkr + 8 * j) * 136 + bnc]),
                           &B[(size_t)(kb + bkr + 8 * j) * Nc + n0 + bnc]);
#pragma unroll
            for (int j = 0; j < 4; j++) {
                int row = arow + 32 * j;
                int gr = m0 + row;
                int ok = (gr < M) ? 16 : 0;
                int grc = (gr < M) ? gr : (M - 1);
                cp_async16z((uint32_t)__cvta_generic_to_shared(&Rn[row * 32 + akc]),
                            &R[(size_t)grc * K + kb + akc], ok);
            }
        }
        asm volatile("cp.async.commit_group;");
        if (kt + 1 < KT) {
            int kb = (kt + 1) << 5;
#pragma unroll
            for (int j = 0; j < 4; j++) {
                int row = arow + 32 * j;
                areg[j] = (m0 + row < M)
                          ? *(const float4*)&G[(size_t)(m0 + row) * K + kb + akc]
                          : make_float4(0.f, 0.f, 0.f, 0.f);
            }
            ccr0 = *(const float4*)&cc[kb + akc];
            ccr1 = *(const float4*)&cc[kb + akc + 2];
        }
        __syncthreads();

        const uint32_t* Bs = smbuf + AS_W + (kt & 1) * BS_W;
#pragma unroll
        for (int ks = 0; ks < 4; ks++) {
            uint32_t af[4][4], bf[4][2];
            const int kk = ks * 8 + (lane & 3);
#pragma unroll
            for (int mt = 0; mt < 4; mt++) {
                int m = wm + mt * 16 + (lane >> 2);
                af[mt][0] = As[m * 36 + kk];
                af[mt][1] = As[(m + 8) * 36 + kk];
                af[mt][2] = As[m * 36 + kk + 4];
                af[mt][3] = As[(m + 8) * 36 + kk + 4];
            }
#pragma unroll
            for (int nt = 0; nt < 4; nt++) {
                int n = wn + nt * 8 + (lane >> 2);
                bf[nt][0] = Bs[kk * 136 + n];
                bf[nt][1] = Bs[(kk + 4) * 136 + n];
            }
#pragma unroll
            for (int mt = 0; mt < 4; mt++)
#pragma unroll
                for (int nt = 0; nt < 4; nt++) {
                    asm volatile(
                        "mma.sync.aligned.m16n8k8.row.col.f32.tf32.tf32.f32 "
                        "{%0,%1,%2,%3}, {%4,%5,%6,%7}, {%8,%9}, {%0,%1,%2,%3};\n"
                        : "+f"(acc[mt][nt][0]), "+f"(acc[mt][nt][1]),
                          "+f"(acc[mt][nt][2]), "+f"(acc[mt][nt][3])
                        : "r"(af[mt][0]), "r"(af[mt][1]), "r"(af[mt][2]), "r"(af[mt][3]),
                          "r"(bf[nt][0]), "r"(bf[nt][1]));
                }
        }
        __syncthreads();
    }

#pragma unroll
    for (int mt = 0; mt < 4; mt++) {
#pragma unroll
        for (int nt = 0; nt < 4; nt++) {
            int r = m0 + wm + mt * 16 + (lane >> 2);
            int c = n0 + wn + nt * 8 + 2 * (lane & 3);
            float b0 = bias ? bias[c] : 0.f;
            float b1 = bias ? bias[c + 1] : 0.f;
            if (r < M) {
                float2 v = make_float2(acc[mt][nt][0] + b0, acc[mt][nt][1] + b1);
                *(float2*)&C[(size_t)r * Nc + c] = v;
            }
            if (r + 8 < M) {
                float2 v = make_float2(acc[mt][nt][2] + b0, acc[mt][nt][3] + b1);
                *(float2*)&C[(size_t)(r + 8) * Nc + c] = v;
            }
        }
    }
}

// ---------------- GAT coefficients ----------------
__global__ void coef1k(const float* __restrict__ asw, const float* __restrict__ adw) {
    int w = (blockIdx.x * blockDim.x + threadIdx.x) >> 5;
    if (w >= NN) return;
    int lane = threadIdx.x & 31;
    int hd = lane >> 2;
    int l2 = lane & 3;
    const float4* hp = (const float4*)(g_h1 + (size_t)w * 384);
    const float4* ap = (const float4*)asw;
    const float4* dp = (const float4*)adw;
    float s = 0.f, d = 0.f;
#pragma unroll
    for (int i = 0; i < 3; i++) {
        int c4 = hd * 12 + l2 + 4 * i;
        float4 v = hp[c4], a = ap[c4], dd = dp[c4];
        s += v.x * a.x + v.y * a.y + v.z * a.z + v.w * a.w;
        d += v.x * dd.x + v.y * dd.y + v.z * dd.z + v.w * dd.w;
    }
    s += __shfl_xor_sync(0xffffffffu, s, 1);
    s += __shfl_xor_sync(0xffffffffu, s, 2);
    d += __shfl_xor_sync(0xffffffffu, d, 1);
    d += __shfl_xor_sync(0xffffffffu, d, 2);
    if (l2 == 0) {
        g_as1[w * 8 + hd] = s;
        g_ad1[w * 8 + hd] = d;
    }
}

__global__ void coef2k(const float* __restrict__ asw, const float* __restrict__ adw) {
    int gw = (blockIdx.x * blockDim.x + threadIdx.x) >> 5;
    if (gw >= NN) return;
    int lane = threadIdx.x & 31;
    const float* hp = g_h2 + (size_t)gw * 256;
    float s = 0.f, d = 0.f;
#pragma unroll
    for (int k = 0; k < 8; k++) {
        int c = lane + 32 * k;
        float v = hp[c];
        s += v * asw[c]; d += v * adw[c];
    }
#pragma unroll
    for (int off = 16; off; off >>= 1) {
        s += __shfl_down_sync(0xffffffffu, s, off);
        d += __shfl_down_sync(0xffffffffu, d, off);
    }
    if (lane == 0) { g_as2[gw] = s; g_ad2[gw] = d; }
}

// ---------------- CSR gather aggregation ----------------
__global__ void gath1k() {
    int w = (blockIdx.x * blockDim.x + threadIdx.x) >> 5;
    if (w >= NN) return;
    int lane = threadIdx.x & 31;
    int beg = g_off[w], end = g_off[w + 1];
    float ad = (lane < 8) ? g_ad1[w * 8 + lane] : 0.f;
    float den = 0.f;
    float4 acc[3];
#pragma unroll
    for (int i = 0; i < 3; i++) acc[i] = make_float4(0.f, 0.f, 0.f, 0.f);

    int s = g_srcl[beg];
    for (int j = beg; j < end; j++) {
        int snext = (j + 1 < end) ? g_srcl[j + 1] : 0;
        float ex = 0.f;
        if (lane < 8) {
            ex = __expf(leaky(g_as1[s * 8 + lane] + ad));
            den += ex;
        }
        const float4* hs = (const float4*)(g_h1 + (size_t)s * 384);
#pragma unroll
        for (int i = 0; i < 3; i++) {
            int c4 = lane + 32 * i;
            float a = __shfl_sync(0xffffffffu, ex, c4 / 12);
            float4 v = hs[c4];
            acc[i].x += v.x * a; acc[i].y += v.y * a;
            acc[i].z += v.z * a; acc[i].w += v.w * a;
        }
        s = snext;
    }
    float4* od = (float4*)(g_gout1 + (size_t)w * 384);
#pragma unroll
    for (int i = 0; i < 3; i++) {
        int c4 = lane + 32 * i;
        float dh = __shfl_sync(0xffffffffu, den, c4 / 12);
        float inv = 1.f / (dh + 1e-16f);
        od[c4] = make_float4(acc[i].x * inv, acc[i].y * inv, acc[i].z * inv, acc[i].w * inv);
    }
}

__global__ void gath2k() {
    int w = (blockIdx.x * blockDim.x + threadIdx.x) >> 5;
    if (w >= NN) return;
    int lane = threadIdx.x & 31;
    int beg = g_off[w], end = g_off[w + 1];
    float ad = g_ad2[w];
    float den = 0.f;
    float4 acc[2];
    acc[0] = make_float4(0.f, 0.f, 0.f, 0.f);
    acc[1] = make_float4(0.f, 0.f, 0.f, 0.f);

    int s = g_srcl[beg];
    for (int j = beg; j < end; j++) {
        int snext = (j + 1 < end) ? g_srcl[j + 1] : 0;
        float ex = __expf(leaky(g_as2[s] + ad));
        den += ex;
        const float4* hs = (const float4*)(g_h2 + (size_t)s * 256);
#pragma unroll
        for (int i = 0; i < 2; i++) {
            float4 v = hs[lane + 32 * i];
            acc[i].x += v.x * ex; acc[i].y += v.y * ex;
            acc[i].z += v.z * ex; acc[i].w += v.w * ex;
        }
        s = snext;
    }
    float inv = 1.f / (den + 1e-16f);
    float4* od = (float4*)(g_gout2 + (size_t)w * 256);
#pragma unroll
    for (int i = 0; i < 2; i++)
        od[lane + 32 * i] = make_float4(acc[i].x * inv, acc[i].y * inv,
                                        acc[i].z * inv, acc[i].w * inv);
}

// ---------------- batch norm partials + fused finalize -> {scale,shift} ------
__global__ void bnpf(const float* __restrict__ X, int C,
                     float* __restrict__ psum, float* __restrict__ pss,
                     float2* __restrict__ cc,
                     const float* __restrict__ gamma, const float* __restrict__ beta,
                     int ctr_idx) {
    int col = blockIdx.x * 32 + threadIdx.x;
    int tt = threadIdx.y * 32 + threadIdx.x;
    float s = 0.f, q = 0.f;
    for (int r = threadIdx.y + blockIdx.y * 8; r < NN; r += 8 * gridDim.y) {
        float v = X[(size_t)r * C + col];
        s += v; q += v * v;
    }
    __shared__ float sh[8][32], sh2[8][32];
    sh[threadIdx.y][threadIdx.x] = s;
    sh2[threadIdx.y][threadIdx.x] = q;
    __syncthreads();
    if (threadIdx.y == 0) {
#pragma unroll
        for (int y = 1; y < 8; y++) { s += sh[y][threadIdx.x]; q += sh2[y][threadIdx.x]; }
        psum[blockIdx.y * C + col] = s;
        pss[blockIdx.y * C + col] = q;
    }
    __threadfence();
    __syncthreads();
    __shared__ bool isLast;
    if (tt == 0)
        isLast = (atomicAdd(&g_ctr[ctr_idx], 1) == (int)(gridDim.x * gridDim.y) - 1);
    __syncthreads();
    if (isLast) {
        __threadfence();
        for (int c = tt; c < C; c += 256) {
            float ss = 0.f, qq = 0.f;
#pragma unroll
            for (int y = 0; y < 16; y++) { ss += psum[y * C + c]; qq += pss[y * C + c]; }
            float m = ss * (1.f / NN);
            float v = qq * (1.f / NN) - m * m;
            float sc = rsqrtf(v + 1e-5f) * gamma[c];
            cc[c] = make_float2(sc, beta[c] - m * sc);
        }
    }
}

// ---------------- pair head ----------------
__global__ void pairk(const int* __restrict__ ei, const int* __restrict__ tid,
                      const float* __restrict__ w4, const float* __restrict__ b4,
                      float* __restrict__ out) {
    int gw = (blockIdx.x * blockDim.x + threadIdx.x) >> 5;
    if (gw >= TEN) return;
    int lane = threadIdx.x & 31;
    int e = tid[gw];
    int s = ei[e], d = ei[EE + e];
    const float* hs = g_hf + (size_t)s * 256;
    const float* hd = g_hf + (size_t)d * 256;
    float acc[7] = {};
#pragma unroll
    for (int k = 0; k < 8; k++) {
        int c = lane + 32 * k;
        float p = hs[c] * hd[c];
        const float* wr = &w4[c * 7];
#pragma unroll
        for (int j = 0; j < 7; j++) acc[j] += p * wr[j];
    }
#pragma unroll
    for (int j = 0; j < 7; j++)
#pragma unroll
        for (int off = 16; off; off >>= 1)
            acc[j] += __shfl_down_sync(0xffffffffu, acc[j], off);
    if (lane == 0) {
#pragma unroll
        for (int j = 0; j < 7; j++) out[(size_t)gw * 7 + j] = acc[j] + b4[j];
    }
}

// ---------------- launch ----------------
extern "C" void kernel_launch(void* const* d_in, const int* in_sizes, int n_in,
                              void* d_out, int out_size) {
    const float* x       = (const float*)d_in[0];
    const int*   ei      = (const int*)d_in[1];
    const int*   teid    = (const int*)d_in[2];
    const float* fc1_w   = (const float*)d_in[3];
    const float* fc1_b   = (const float*)d_in[4];
    const float* fc5_w   = (const float*)d_in[5];
    const float* fc5_b   = (const float*)d_in[6];
    const float* fc2_w   = (const float*)d_in[7];
    const float* fc2_b   = (const float*)d_in[8];
    const float* fc4_w   = (const float*)d_in[9];
    const float* fc4_b   = (const float*)d_in[10];
    const float* gat1_w  = (const float*)d_in[11];
    const float* gat1_as = (const float*)d_in[12];
    const float* gat1_ad = (const float*)d_in[13];
    /* gat1_b unused: BN-invariant */
    const float* gat2_w  = (const float*)d_in[15];
    const float* gat2_as = (const float*)d_in[16];
    const float* gat2_ad = (const float*)d_in[17];
    /* gat2_b unused: BN-invariant */
    const float* bn1_g   = (const float*)d_in[19];
    const float* bn1_b   = (const float*)d_in[20];
    const float* bn2_g   = (const float*)d_in[21];
    const float* bn2_b   = (const float*)d_in[22];
    float* out = (float*)d_out;

    float *p_w1c, *p_b1c, *p_w5r, *p_wg2r, *p_w2r;
    float *p_h1, *p_h5, *p_h2, *p_hf, *p_gout1, *p_gout2;
    float *p_psum1, *p_pss1, *p_psum2, *p_pss2;
    float2 *p_cc1, *p_cc2;
    cudaGetSymbolAddress((void**)&p_w1c, g_w1c);
    cudaGetSymbolAddress((void**)&p_b1c, g_b1c);
    cudaGetSymbolAddress((void**)&p_w5r, g_w5r);
    cudaGetSymbolAddress((void**)&p_wg2r, g_wg2r);
    cudaGetSymbolAddress((void**)&p_w2r, g_w2r);
    cudaGetSymbolAddress((void**)&p_h1, g_h1);
    cudaGetSymbolAddress((void**)&p_h5, g_h5);
    cudaGetSymbolAddress((void**)&p_h2, g_h2);
    cudaGetSymbolAddress((void**)&p_hf, g_hf);
    cudaGetSymbolAddress((void**)&p_gout1, g_gout1);
    cudaGetSymbolAddress((void**)&p_gout2, g_gout2);
    cudaGetSymbolAddress((void**)&p_psum1, g_psum1);
    cudaGetSymbolAddress((void**)&p_pss1, g_pss1);
    cudaGetSymbolAddress((void**)&p_psum2, g_psum2);
    cudaGetSymbolAddress((void**)&p_pss2, g_pss2);
    cudaGetSymbolAddress((void**)&p_cc1, g_cc1);
    cudaGetSymbolAddress((void**)&p_cc2, g_cc2);

    cudaFuncSetAttribute(gemm_cp, cudaFuncAttributeMaxDynamicSharedMemorySize, GEMM_SMEM);
    cudaFuncSetAttribute(gemm_bn, cudaFuncAttributeMaxDynamicSharedMemorySize, GEMM_BN_SMEM);

    const int MB = (NN + 127) / 128;  // 79

    setupA<<<40, 256>>>();
    setupB<<<NB_ALL, 256>>>(fc1_w, gat1_w, fc1_b, fc5_w, gat2_w, fc2_w, ei);
    fillk<<<NB_FILL + NB_RW1, 256>>>(ei);

    // h1 = x @ w1c + b1c
    gemm_cp<<<dim3(3, MB), 256, GEMM_SMEM>>>(
        x, (const uint32_t*)p_w1c, p_b1c, p_h1, NN, 384, 384);

    coef1k<<<(NN * 32 + 255) / 256, 256>>>(gat1_as, gat1_ad);
    gath1k<<<(NN * 32 + 255) / 256, 256>>>();

    bnpf<<<dim3(12, 16), dim3(32, 8)>>>(p_gout1, 384, p_psum1, p_pss1,
                                        p_cc1, bn1_g, bn1_b, 1);

    // h5 = relu(x + bn(gout1)) @ fc5_w + fc5_b
    gemm_bn<<<dim3(2, MB), 256, GEMM_BN_SMEM>>>(
        p_gout1, x, p_cc1, (const uint32_t*)p_w5r, fc5_b, p_h5, NN, 384, 256);
    gemm_cp<<<dim3(2, MB), 256, GEMM_SMEM>>>(
        p_h5, (const uint32_t*)p_wg2r, nullptr, p_h2, NN, 256, 256);

    coef2k<<<(NN * 32 + 255) / 256, 256>>>(gat2_as, gat2_ad);
    gath2k<<<(NN * 32 + 255) / 256, 256>>>();

    bnpf<<<dim3(8, 16), dim3(32, 8)>>>(p_gout2, 256, p_psum2, p_pss2,
                                       p_cc2, bn2_g, bn2_b, 2);

    // hf = relu(h5 + bn(gout2)) @ fc2_w + fc2_b
    gemm_bn<<<dim3(2, MB), 256, GEMM_BN_SMEM>>>(
        p_gout2, p_h5, p_cc2, (const uint32_t*)p_w2r, fc2_b, p_hf, NN, 256, 256);

    pairk<<<(TEN * 32 + 255) / 256, 256>>>(ei, teid, fc4_w, fc4_b, out);
}